// round 1
// baseline (speedup 1.0000x reference)
#include <cuda_runtime.h>

#define H 768
#define SQ 384
#define BB 2
#define NHEADS 12
#define DHEAD 64
#define BS (BB*SQ)   // 768 rows total

// Scratch (allocation-free rule: __device__ globals)
__device__ float g_q[BS*H];
__device__ float g_k[BS*H];
__device__ float g_v[BS*H];
__device__ float g_ctx[BS*H];

__device__ __forceinline__ float frcp_approx(float x){ float r; asm("rcp.approx.ftz.f32 %0, %1;" : "=f"(r) : "f"(x)); return r; }
__device__ __forceinline__ float fsqrt_approx(float x){ float r; asm("sqrt.approx.f32 %0, %1;" : "=f"(r) : "f"(x)); return r; }
__device__ __forceinline__ float frsqrt_approx(float x){ float r; asm("rsqrt.approx.f32 %0, %1;" : "=f"(r) : "f"(x)); return r; }

// ---------------------------------------------------------------------------
// Kernel 1: QKV projections.  out[z][m,n] = sum_k x[m,k] * W[z][n,k] + b[z][n]
// Both operands K-major -> load both tiles the same way.
// grid (12, 12, 3), block 256. BM=BN=64, BK=16, 4x4 per thread.
// ---------------------------------------------------------------------------
__global__ __launch_bounds__(256) void qkv_gemm(
    const float* __restrict__ x,
    const float* __restrict__ Wq, const float* __restrict__ bq,
    const float* __restrict__ Wk, const float* __restrict__ bk,
    const float* __restrict__ Wv, const float* __restrict__ bv)
{
    const float* W; const float* bias; float* out;
    if (blockIdx.z == 0)      { W = Wq; bias = bq; out = g_q; }
    else if (blockIdx.z == 1) { W = Wk; bias = bk; out = g_k; }
    else                      { W = Wv; bias = bv; out = g_v; }

    __shared__ float As[16][64];   // As[k][m]
    __shared__ float Bs[16][64];   // Bs[k][n]

    const int tid = threadIdx.x;
    const int m0 = blockIdx.x * 64, n0 = blockIdx.y * 64;
    const int lr = tid >> 2;          // 0..63 row within tile
    const int lc = (tid & 3) << 2;    // 0,4,8,12 col4 within k-slab
    const int tx = tid & 15, ty = tid >> 4;

    float acc[4][4] = {};

    const float* xp = x + (m0 + lr) * H + lc;
    const float* wp = W + (n0 + lr) * H + lc;

    for (int k0 = 0; k0 < H; k0 += 16) {
        float4 av = *(const float4*)(xp + k0);
        float4 bv4 = *(const float4*)(wp + k0);
        As[lc+0][lr] = av.x;  As[lc+1][lr] = av.y;  As[lc+2][lr] = av.z;  As[lc+3][lr] = av.w;
        Bs[lc+0][lr] = bv4.x; Bs[lc+1][lr] = bv4.y; Bs[lc+2][lr] = bv4.z; Bs[lc+3][lr] = bv4.w;
        __syncthreads();
        #pragma unroll
        for (int k = 0; k < 16; k++) {
            float a[4], b[4];
            *(float4*)a = *(const float4*)&As[k][ty*4];
            *(float4*)b = *(const float4*)&Bs[k][tx*4];
            #pragma unroll
            for (int i = 0; i < 4; i++)
                #pragma unroll
                for (int j = 0; j < 4; j++)
                    acc[i][j] = fmaf(a[i], b[j], acc[i][j]);
        }
        __syncthreads();
    }

    #pragma unroll
    for (int i = 0; i < 4; i++) {
        int m = m0 + ty*4 + i;
        #pragma unroll
        for (int j = 0; j < 4; j++) {
            int n = n0 + tx*4 + j;
            out[m*H + n] = acc[i][j] + bias[n];
        }
    }
}

// ---------------------------------------------------------------------------
// Kernel 2: attention with p=-2 distance scores.
// grid (S/64=6, NH=12, B=2), block 256.
// Dynamic smem: qs[64][65] + ks[64][65] (reused for V) + sc[64][385] + rowsum[64]
// ---------------------------------------------------------------------------
#define SCW 385

__global__ __launch_bounds__(256) void attn_kernel()
{
    extern __shared__ float sm[];
    float* qs = sm;                       // 64*65
    float* ks = sm + 64*65;               // 64*65  (K tiles, then V tiles)
    float* sc = sm + 2*64*65;             // 64*385 scores -> probs
    float* rowsum = sc + 64*SCW;          // 64

    const int tid = threadIdx.x;
    const int b = blockIdx.z, h = blockIdx.y;
    const int i0 = blockIdx.x * 64;

    const float* Qb = g_q + (size_t)(b*SQ)*H + h*DHEAD;
    const float* Kb = g_k + (size_t)(b*SQ)*H + h*DHEAD;
    const float* Vb = g_v + (size_t)(b*SQ)*H + h*DHEAD;

    // Load Q tile [64][64] (rows i0..i0+63, this head's 64 dims)
    for (int idx = tid; idx < 64*16; idx += 256) {
        int i = idx >> 4, c4 = (idx & 15) << 2;
        float4 v = *(const float4*)&Qb[(size_t)(i0+i)*H + c4];
        qs[i*65+c4+0] = v.x; qs[i*65+c4+1] = v.y; qs[i*65+c4+2] = v.z; qs[i*65+c4+3] = v.w;
    }

    const int tx = tid & 15, ty = tid >> 4;

    // ---- Phase 1: scores ----
    for (int jt = 0; jt < 6; jt++) {
        int j0 = jt * 64;
        __syncthreads();   // previous tile's ks consumers done (also covers qs on jt=0 after 2nd sync)
        for (int idx = tid; idx < 64*16; idx += 256) {
            int j = idx >> 4, c4 = (idx & 15) << 2;
            float4 v = *(const float4*)&Kb[(size_t)(j0+j)*H + c4];
            ks[j*65+c4+0] = v.x; ks[j*65+c4+1] = v.y; ks[j*65+c4+2] = v.z; ks[j*65+c4+3] = v.w;
        }
        __syncthreads();

        float acc[4][4] = {};
        #pragma unroll 8
        for (int d = 0; d < 64; d++) {
            float qv[4], kv[4];
            #pragma unroll
            for (int i = 0; i < 4; i++) qv[i] = qs[(ty*4+i)*65 + d];
            #pragma unroll
            for (int j = 0; j < 4; j++) kv[j] = ks[(tx*4+j)*65 + d];
            #pragma unroll
            for (int i = 0; i < 4; i++)
                #pragma unroll
                for (int j = 0; j < 4; j++) {
                    float dd = qv[i] - kv[j];
                    acc[i][j] += frcp_approx(dd * dd);
                }
        }
        #pragma unroll
        for (int i = 0; i < 4; i++)
            #pragma unroll
            for (int j = 0; j < 4; j++)
                sc[(ty*4+i)*SCW + j0 + tx*4 + j] = -frsqrt_approx(fsqrt_approx(acc[i][j]));
    }
    __syncthreads();

    // ---- Phase 2: softmax rows (store unnormalized probs + rowsum) ----
    {
        const int wid = tid >> 5, lane = tid & 31;
        for (int i = wid; i < 64; i += 8) {
            float m = -3.402823466e38f;
            for (int j = lane; j < SQ; j += 32) m = fmaxf(m, sc[i*SCW + j]);
            #pragma unroll
            for (int o = 16; o; o >>= 1) m = fmaxf(m, __shfl_xor_sync(0xffffffffu, m, o));
            float s = 0.f;
            for (int j = lane; j < SQ; j += 32) {
                float p = __expf(sc[i*SCW + j] - m);
                sc[i*SCW + j] = p;
                s += p;
            }
            #pragma unroll
            for (int o = 16; o; o >>= 1) s += __shfl_xor_sync(0xffffffffu, s, o);
            if (lane == 0) rowsum[i] = s;
        }
    }
    __syncthreads();

    // ---- Phase 3: ctx = P @ V ----
    float acc2[4][4] = {};
    for (int jt = 0; jt < 6; jt++) {
        int j0 = jt * 64;
        for (int idx = tid; idx < 64*16; idx += 256) {
            int j = idx >> 4, c4 = (idx & 15) << 2;
            float4 v = *(const float4*)&Vb[(size_t)(j0+j)*H + c4];
            ks[j*65+c4+0] = v.x; ks[j*65+c4+1] = v.y; ks[j*65+c4+2] = v.z; ks[j*65+c4+3] = v.w;
        }
        __syncthreads();
        #pragma unroll 4
        for (int j = 0; j < 64; j++) {
            float pv[4], vv[4];
            #pragma unroll
            for (int i = 0; i < 4; i++) pv[i] = sc[(ty*4+i)*SCW + j0 + j];
            #pragma unroll
            for (int d = 0; d < 4; d++) vv[d] = ks[j*65 + tx*4 + d];
            #pragma unroll
            for (int i = 0; i < 4; i++)
                #pragma unroll
                for (int d = 0; d < 4; d++)
                    acc2[i][d] = fmaf(pv[i], vv[d], acc2[i][d]);
        }
        __syncthreads();
    }

    #pragma unroll
    for (int i = 0; i < 4; i++) {
        float rs = frcp_approx(rowsum[ty*4 + i]);
        int row = i0 + ty*4 + i;
        #pragma unroll
        for (int d = 0; d < 4; d++)
            g_ctx[(size_t)(b*SQ + row)*H + h*DHEAD + tx*4 + d] = acc2[i][d] * rs;
    }
}

// ---------------------------------------------------------------------------
// Kernel 3: residual + LayerNorm. One block per row.
// ---------------------------------------------------------------------------
__global__ __launch_bounds__(256) void ln_kernel(
    const float* __restrict__ x, const float* __restrict__ gam,
    const float* __restrict__ bet, float* __restrict__ out)
{
    const int r = blockIdx.x;
    const float* xr = x + (size_t)r * H;
    const float* cr = g_ctx + (size_t)r * H;
    const int tid = threadIdx.x;

    __shared__ float redS[8], redQ[8];

    float y[3];
    float s = 0.f, ss = 0.f;
    #pragma unroll
    for (int k = 0; k < 3; k++) {
        int j = tid + k * 256;
        y[k] = xr[j] + cr[j];
        s += y[k];
        ss += y[k] * y[k];
    }
    #pragma unroll
    for (int o = 16; o; o >>= 1) {
        s  += __shfl_xor_sync(0xffffffffu, s, o);
        ss += __shfl_xor_sync(0xffffffffu, ss, o);
    }
    const int wid = tid >> 5, lane = tid & 31;
    if (lane == 0) { redS[wid] = s; redQ[wid] = ss; }
    __syncthreads();
    if (tid == 0) {
        float a = 0.f, b2 = 0.f;
        #pragma unroll
        for (int w = 0; w < 8; w++) { a += redS[w]; b2 += redQ[w]; }
        redS[0] = a; redQ[0] = b2;
    }
    __syncthreads();
    const float mu  = redS[0] * (1.f / (float)H);
    const float var = redQ[0] * (1.f / (float)H) - mu * mu;
    const float inv = rsqrtf(var + 1e-12f);

    #pragma unroll
    for (int k = 0; k < 3; k++) {
        int j = tid + k * 256;
        out[(size_t)r * H + j] = (y[k] - mu) * inv * gam[j] + bet[j];
    }
}

// ---------------------------------------------------------------------------
extern "C" void kernel_launch(void* const* d_in, const int* in_sizes, int n_in,
                              void* d_out, int out_size)
{
    const float* x   = (const float*)d_in[0];
    const float* Wq  = (const float*)d_in[1];
    const float* bq  = (const float*)d_in[2];
    const float* Wk  = (const float*)d_in[3];
    const float* bk  = (const float*)d_in[4];
    const float* Wv  = (const float*)d_in[5];
    const float* bv  = (const float*)d_in[6];
    const float* lng = (const float*)d_in[7];
    const float* lnb = (const float*)d_in[8];
    float* out = (float*)d_out;

    // 1) QKV projections
    qkv_gemm<<<dim3(12, 12, 3), 256>>>(x, Wq, bq, Wk, bk, Wv, bv);

    // 2) attention
    size_t smem = (size_t)(2*64*65 + 64*SCW + 64) * sizeof(float);   // ~129 KB
    cudaFuncSetAttribute(attn_kernel, cudaFuncAttributeMaxDynamicSharedMemorySize, (int)smem);
    attn_kernel<<<dim3(6, NHEADS, BB), 256, smem>>>();

    // 3) residual + LayerNorm
    ln_kernel<<<BS, 256>>>(x, lng, lnb, out);
}

// round 2
// speedup vs baseline: 1.1744x; 1.1744x over previous
#include <cuda_runtime.h>

#define H 768
#define SQ 384
#define BB 2
#define NHEADS 12
#define DHEAD 64
#define BS (BB*SQ)   // 768 rows total

// Scratch (allocation-free rule: __device__ globals)
__device__ float g_q[BS*H];
__device__ float g_k[BS*H];
__device__ float g_v[BS*H];
__device__ float g_ctx[BS*H];

__device__ __forceinline__ float frcp_approx(float x){ float r; asm("rcp.approx.ftz.f32 %0, %1;" : "=f"(r) : "f"(x)); return r; }
__device__ __forceinline__ float fsqrt_approx(float x){ float r; asm("sqrt.approx.f32 %0, %1;" : "=f"(r) : "f"(x)); return r; }
__device__ __forceinline__ float frsqrt_approx(float x){ float r; asm("rsqrt.approx.f32 %0, %1;" : "=f"(r) : "f"(x)); return r; }

// ---------------------------------------------------------------------------
// Kernel 1: fused QKV projection as one 768 x 2304 GEMM.
// out[m, ng] = sum_k x[m,k] * W[z][n,k] + b[z][n],  z = ng/768, n = ng%768
// CTA tile 128(M) x 96(N), k-slab 32, 256 threads, 8x6 register tile.
// grid (6, 24) = 144 CTAs = one wave on 148 SMs.
// ---------------------------------------------------------------------------
#define ASTR 132   // As row stride (padded, 16B-aligned)
#define BSTR 100   // Bs row stride (padded, 8B-aligned)

__global__ __launch_bounds__(256) void qkv_gemm(
    const float* __restrict__ x,
    const float* __restrict__ Wq, const float* __restrict__ bq,
    const float* __restrict__ Wk, const float* __restrict__ bk,
    const float* __restrict__ Wv, const float* __restrict__ bv)
{
    __shared__ float As[32 * ASTR];   // As[k][m], 128 m
    __shared__ float Bs[32 * BSTR];   // Bs[k][n], 96 n

    const int tid = threadIdx.x;
    const int m0 = blockIdx.x * 128;
    const int ng0 = blockIdx.y * 96;           // global n in [0, 2304)
    const int z  = ng0 / 768;                  // which projection
    const int n0 = ng0 - z * 768;              // local n

    const float* W; const float* bias; float* out;
    if (z == 0)      { W = Wq; bias = bq; out = g_q; }
    else if (z == 1) { W = Wk; bias = bk; out = g_k; }
    else             { W = Wv; bias = bv; out = g_v; }

    const int tx = tid & 15;     // n group: 6 cols each
    const int ty = tid >> 4;     // m group: 8 rows each

    // fill indexing
    const int am = tid >> 1;                 // unused pattern; use idx loop instead
    (void)am;

    float acc[8][6] = {};

    // register prefetch buffers: A 4 float4, B 3 float4
    float4 pa[4], pb[3];

    // ---- load slab 0 ----
    {
        const int k0 = 0;
        #pragma unroll
        for (int it = 0; it < 4; it++) {
            int idx = tid + it * 256;          // 0..1023
            int m = idx >> 3, kq = (idx & 7) << 2;
            pa[it] = *(const float4*)&x[(size_t)(m0 + m) * H + k0 + kq];
        }
        #pragma unroll
        for (int it = 0; it < 3; it++) {
            int idx = tid + it * 256;          // 0..767
            int n = idx >> 3, kq = (idx & 7) << 2;
            pb[it] = *(const float4*)&W[(size_t)(n0 + n) * H + k0 + kq];
        }
    }

    for (int s = 0; s < 24; s++) {
        __syncthreads();  // previous compute done before overwrite
        // store prefetched slab to smem (transposed: [k][m] / [k][n])
        #pragma unroll
        for (int it = 0; it < 4; it++) {
            int idx = tid + it * 256;
            int m = idx >> 3, kq = (idx & 7) << 2;
            As[(kq+0)*ASTR + m] = pa[it].x;
            As[(kq+1)*ASTR + m] = pa[it].y;
            As[(kq+2)*ASTR + m] = pa[it].z;
            As[(kq+3)*ASTR + m] = pa[it].w;
        }
        #pragma unroll
        for (int it = 0; it < 3; it++) {
            int idx = tid + it * 256;
            int n = idx >> 3, kq = (idx & 7) << 2;
            Bs[(kq+0)*BSTR + n] = pb[it].x;
            Bs[(kq+1)*BSTR + n] = pb[it].y;
            Bs[(kq+2)*BSTR + n] = pb[it].z;
            Bs[(kq+3)*BSTR + n] = pb[it].w;
        }
        __syncthreads();

        // prefetch next slab while computing this one
        if (s < 23) {
            const int k0 = (s + 1) * 32;
            #pragma unroll
            for (int it = 0; it < 4; it++) {
                int idx = tid + it * 256;
                int m = idx >> 3, kq = (idx & 7) << 2;
                pa[it] = *(const float4*)&x[(size_t)(m0 + m) * H + k0 + kq];
            }
            #pragma unroll
            for (int it = 0; it < 3; it++) {
                int idx = tid + it * 256;
                int n = idx >> 3, kq = (idx & 7) << 2;
                pb[it] = *(const float4*)&W[(size_t)(n0 + n) * H + k0 + kq];
            }
        }

        #pragma unroll 8
        for (int k = 0; k < 32; k++) {
            float ar[8], br[6];
            *(float4*)&ar[0] = *(const float4*)&As[k*ASTR + ty*8];
            *(float4*)&ar[4] = *(const float4*)&As[k*ASTR + ty*8 + 4];
            *(float2*)&br[0] = *(const float2*)&Bs[k*BSTR + tx*6];
            *(float2*)&br[2] = *(const float2*)&Bs[k*BSTR + tx*6 + 2];
            *(float2*)&br[4] = *(const float2*)&Bs[k*BSTR + tx*6 + 4];
            #pragma unroll
            for (int i = 0; i < 8; i++)
                #pragma unroll
                for (int j = 0; j < 6; j++)
                    acc[i][j] = fmaf(ar[i], br[j], acc[i][j]);
        }
    }

    #pragma unroll
    for (int i = 0; i < 8; i++) {
        int m = m0 + ty*8 + i;
        #pragma unroll
        for (int j = 0; j < 6; j++) {
            int n = n0 + tx*6 + j;
            out[(size_t)m * H + n] = acc[i][j] + bias[n];
        }
    }
}

// ---------------------------------------------------------------------------
// Kernel 2: attention with p=-2 distance scores.
// grid (S/64=6, NH=12, B=2), block 256.
// Paired reciprocal: 1/a + 1/b = (a+b)/(a*b)  -> one MUFU.RCP per 2 dims.
// K tile stored transposed [d][j] so the d-pair loop reads it with LDS.128.
// ---------------------------------------------------------------------------
#define QSTR 68    // qs / vs row stride (16B aligned)
#define KSTR 68    // ks_t row stride
#define SCW 385

__global__ __launch_bounds__(256) void attn_kernel()
{
    extern __shared__ float sm[];
    float* qs = sm;                       // [64][QSTR]  row-major Q
    float* ks = sm + 64*QSTR;             // [64][KSTR]  K transposed [d][j]; later V row-major
    float* sc = sm + 2*64*QSTR;           // [64][SCW]   scores -> probs
    float* rowsum = sc + 64*SCW;          // 64

    const int tid = threadIdx.x;
    const int b = blockIdx.z, h = blockIdx.y;
    const int i0 = blockIdx.x * 64;

    const float* Qb = g_q + (size_t)(b*SQ)*H + h*DHEAD;
    const float* Kb = g_k + (size_t)(b*SQ)*H + h*DHEAD;
    const float* Vb = g_v + (size_t)(b*SQ)*H + h*DHEAD;

    // Load Q tile [64][64] row-major
    for (int idx = tid; idx < 64*16; idx += 256) {
        int i = idx >> 4, c4 = (idx & 15) << 2;
        float4 v = *(const float4*)&Qb[(size_t)(i0+i)*H + c4];
        *(float4*)&qs[i*QSTR + c4] = v;
    }

    const int tx = tid & 15, ty = tid >> 4;

    // ---- Phase 1: scores ----
    for (int jt = 0; jt < 6; jt++) {
        int j0 = jt * 64;
        __syncthreads();   // previous tile's ks consumers done
        // K tile transposed: ks[d][j]
        for (int idx = tid; idx < 64*16; idx += 256) {
            int j = idx >> 4, d4 = (idx & 15) << 2;
            float4 v = *(const float4*)&Kb[(size_t)(j0+j)*H + d4];
            ks[(d4+0)*KSTR + j] = v.x;
            ks[(d4+1)*KSTR + j] = v.y;
            ks[(d4+2)*KSTR + j] = v.z;
            ks[(d4+3)*KSTR + j] = v.w;
        }
        __syncthreads();

        float acc[4][4] = {};
        #pragma unroll 4
        for (int d = 0; d < 64; d += 2) {
            float k0r[4], k1r[4];
            *(float4*)k0r = *(const float4*)&ks[d*KSTR + tx*4];
            *(float4*)k1r = *(const float4*)&ks[(d+1)*KSTR + tx*4];
            float2 qv[4];
            #pragma unroll
            for (int i = 0; i < 4; i++)
                qv[i] = *(const float2*)&qs[(ty*4+i)*QSTR + d];
            #pragma unroll
            for (int i = 0; i < 4; i++)
                #pragma unroll
                for (int j = 0; j < 4; j++) {
                    float d1 = qv[i].x - k0r[j];
                    float d2 = qv[i].y - k1r[j];
                    float a = d1 * d1;
                    float bb = d2 * d2;
                    acc[i][j] = fmaf(a + bb, frcp_approx(a * bb), acc[i][j]);
                }
        }
        #pragma unroll
        for (int i = 0; i < 4; i++)
            #pragma unroll
            for (int j = 0; j < 4; j++)
                sc[(ty*4+i)*SCW + j0 + tx*4 + j] = -frsqrt_approx(fsqrt_approx(acc[i][j]));
    }
    __syncthreads();

    // ---- Phase 2: softmax rows (store unnormalized probs + rowsum) ----
    {
        const int wid = tid >> 5, lane = tid & 31;
        for (int i = wid; i < 64; i += 8) {
            float m = -3.402823466e38f;
            for (int j = lane; j < SQ; j += 32) m = fmaxf(m, sc[i*SCW + j]);
            #pragma unroll
            for (int o = 16; o; o >>= 1) m = fmaxf(m, __shfl_xor_sync(0xffffffffu, m, o));
            float s = 0.f;
            for (int j = lane; j < SQ; j += 32) {
                float p = __expf(sc[i*SCW + j] - m);
                sc[i*SCW + j] = p;
                s += p;
            }
            #pragma unroll
            for (int o = 16; o; o >>= 1) s += __shfl_xor_sync(0xffffffffu, s, o);
            if (lane == 0) rowsum[i] = s;
        }
    }
    __syncthreads();

    // ---- Phase 3: ctx = P @ V ----  (V row-major in ks buffer)
    float acc2[4][4] = {};
    for (int jt = 0; jt < 6; jt++) {
        int j0 = jt * 64;
        for (int idx = tid; idx < 64*16; idx += 256) {
            int j = idx >> 4, d4 = (idx & 15) << 2;
            float4 v = *(const float4*)&Vb[(size_t)(j0+j)*H + d4];
            *(float4*)&ks[j*QSTR + d4] = v;
        }
        __syncthreads();
        #pragma unroll 4
        for (int j = 0; j < 64; j++) {
            float vv[4];
            *(float4*)vv = *(const float4*)&ks[j*QSTR + tx*4];
            float pv[4];
            #pragma unroll
            for (int i = 0; i < 4; i++) pv[i] = sc[(ty*4+i)*SCW + j0 + j];
            #pragma unroll
            for (int i = 0; i < 4; i++)
                #pragma unroll
                for (int d = 0; d < 4; d++)
                    acc2[i][d] = fmaf(pv[i], vv[d], acc2[i][d]);
        }
        __syncthreads();
    }

    #pragma unroll
    for (int i = 0; i < 4; i++) {
        float rs = frcp_approx(rowsum[ty*4 + i]);
        int row = i0 + ty*4 + i;
        #pragma unroll
        for (int d = 0; d < 4; d++)
            g_ctx[(size_t)(b*SQ + row)*H + h*DHEAD + tx*4 + d] = acc2[i][d] * rs;
    }
}

// ---------------------------------------------------------------------------
// Kernel 3: residual + LayerNorm. One block per row.
// ---------------------------------------------------------------------------
__global__ __launch_bounds__(256) void ln_kernel(
    const float* __restrict__ x, const float* __restrict__ gam,
    const float* __restrict__ bet, float* __restrict__ out)
{
    const int r = blockIdx.x;
    const float* xr = x + (size_t)r * H;
    const float* cr = g_ctx + (size_t)r * H;
    const int tid = threadIdx.x;

    __shared__ float redS[8], redQ[8];

    float y[3];
    float s = 0.f, ss = 0.f;
    #pragma unroll
    for (int k = 0; k < 3; k++) {
        int j = tid + k * 256;
        y[k] = xr[j] + cr[j];
        s += y[k];
        ss += y[k] * y[k];
    }
    #pragma unroll
    for (int o = 16; o; o >>= 1) {
        s  += __shfl_xor_sync(0xffffffffu, s, o);
        ss += __shfl_xor_sync(0xffffffffu, ss, o);
    }
    const int wid = tid >> 5, lane = tid & 31;
    if (lane == 0) { redS[wid] = s; redQ[wid] = ss; }
    __syncthreads();
    if (tid == 0) {
        float a = 0.f, b2 = 0.f;
        #pragma unroll
        for (int w = 0; w < 8; w++) { a += redS[w]; b2 += redQ[w]; }
        redS[0] = a; redQ[0] = b2;
    }
    __syncthreads();
    const float mu  = redS[0] * (1.f / (float)H);
    const float var = redQ[0] * (1.f / (float)H) - mu * mu;
    const float inv = rsqrtf(var + 1e-12f);

    #pragma unroll
    for (int k = 0; k < 3; k++) {
        int j = tid + k * 256;
        out[(size_t)r * H + j] = (y[k] - mu) * inv * gam[j] + bet[j];
    }
}

// ---------------------------------------------------------------------------
extern "C" void kernel_launch(void* const* d_in, const int* in_sizes, int n_in,
                              void* d_out, int out_size)
{
    const float* x   = (const float*)d_in[0];
    const float* Wq  = (const float*)d_in[1];
    const float* bq  = (const float*)d_in[2];
    const float* Wk  = (const float*)d_in[3];
    const float* bk  = (const float*)d_in[4];
    const float* Wv  = (const float*)d_in[5];
    const float* bv  = (const float*)d_in[6];
    const float* lng = (const float*)d_in[7];
    const float* lnb = (const float*)d_in[8];
    float* out = (float*)d_out;

    // 1) fused QKV projection: grid (6 m-tiles, 24 n-tiles) = 144 CTAs
    qkv_gemm<<<dim3(6, 24), 256>>>(x, Wq, bq, Wk, bk, Wv, bv);

    // 2) attention
    size_t smem = (size_t)(2*64*QSTR + 64*SCW + 64) * sizeof(float);   // ~130.5 KB
    cudaFuncSetAttribute(attn_kernel, cudaFuncAttributeMaxDynamicSharedMemorySize, (int)smem);
    attn_kernel<<<dim3(6, NHEADS, BB), 256, smem>>>();

    // 3) residual + LayerNorm
    ln_kernel<<<BS, 256>>>(x, lng, lnb, out);
}

// round 4
// speedup vs baseline: 1.3023x; 1.1089x over previous
#include <cuda_runtime.h>

#define H 768
#define SQ 384
#define BB 2
#define NHEADS 12
#define DHEAD 64
#define BS (BB*SQ)   // 768 rows total

// Scratch (allocation-free rule: __device__ globals)
__device__ float g_q[BS*H];
__device__ float g_k[BS*H];
__device__ float g_v[BS*H];
__device__ float g_ctx[BS*H];

__device__ __forceinline__ float frcp_approx(float x){ float r; asm("rcp.approx.ftz.f32 %0, %1;" : "=f"(r) : "f"(x)); return r; }
__device__ __forceinline__ float fsqrt_approx(float x){ float r; asm("sqrt.approx.f32 %0, %1;" : "=f"(r) : "f"(x)); return r; }
__device__ __forceinline__ float frsqrt_approx(float x){ float r; asm("rsqrt.approx.f32 %0, %1;" : "=f"(r) : "f"(x)); return r; }

// ---- packed fp32x2 ops (Blackwell FFMA2 path; IEEE fp32 per lane) ----
union F2U { float2 f; unsigned long long u; };
__device__ __forceinline__ float2 f2fma(float2 a, float2 b, float2 c){
    F2U A, Bv, C, R; A.f = a; Bv.f = b; C.f = c;
    asm("fma.rn.f32x2 %0, %1, %2, %3;" : "=l"(R.u) : "l"(A.u), "l"(Bv.u), "l"(C.u));
    return R.f;
}
__device__ __forceinline__ float2 f2add(float2 a, float2 b){
    F2U A, Bv, R; A.f = a; Bv.f = b;
    asm("add.rn.f32x2 %0, %1, %2;" : "=l"(R.u) : "l"(A.u), "l"(Bv.u));
    return R.f;
}
__device__ __forceinline__ float2 f2mul(float2 a, float2 b){
    F2U A, Bv, R; A.f = a; Bv.f = b;
    asm("mul.rn.f32x2 %0, %1, %2;" : "=l"(R.u) : "l"(A.u), "l"(Bv.u));
    return R.f;
}

// ---------------------------------------------------------------------------
// Kernel 1: fused QKV projection as one 768 x 2304 GEMM.
// CTA tile 128(M) x 96(N), k-slab 32, 256 threads, 8x6 register tile,
// inner product via fma.rn.f32x2 packed over M pairs.
// grid (6, 24) = 144 CTAs = one wave on 148 SMs.
// ---------------------------------------------------------------------------
#define ASTR 132   // As row stride (padded, 16B-aligned)
#define BSTR 100   // Bs row stride (padded, 8B-aligned)

__global__ __launch_bounds__(256) void qkv_gemm(
    const float* __restrict__ x,
    const float* __restrict__ Wq, const float* __restrict__ bq,
    const float* __restrict__ Wk, const float* __restrict__ bk,
    const float* __restrict__ Wv, const float* __restrict__ bv)
{
    __shared__ float As[32 * ASTR];   // As[k][m], 128 m
    __shared__ float Bs[32 * BSTR];   // Bs[k][n], 96 n

    const int tid = threadIdx.x;
    const int m0 = blockIdx.x * 128;
    const int ng0 = blockIdx.y * 96;           // global n in [0, 2304)
    const int z  = ng0 / 768;                  // which projection
    const int n0 = ng0 - z * 768;              // local n

    const float* W; const float* bias; float* out;
    if (z == 0)      { W = Wq; bias = bq; out = g_q; }
    else if (z == 1) { W = Wk; bias = bk; out = g_k; }
    else             { W = Wv; bias = bv; out = g_v; }

    const int tx = tid & 15;     // n group: 6 cols each
    const int ty = tid >> 4;     // m group: 8 rows each

    float2 acc[4][6];            // packed over m pairs: acc[ip][j] = {m=2ip, m=2ip+1}
    #pragma unroll
    for (int i = 0; i < 4; i++)
        #pragma unroll
        for (int j = 0; j < 6; j++) acc[i][j] = make_float2(0.f, 0.f);

    float4 pa[4], pb[3];

    // ---- prefetch slab 0 ----
    #pragma unroll
    for (int it = 0; it < 4; it++) {
        int idx = tid + it * 256;
        int m = idx >> 3, kq = (idx & 7) << 2;
        pa[it] = *(const float4*)&x[(size_t)(m0 + m) * H + kq];
    }
    #pragma unroll
    for (int it = 0; it < 3; it++) {
        int idx = tid + it * 256;
        int n = idx >> 3, kq = (idx & 7) << 2;
        pb[it] = *(const float4*)&W[(size_t)(n0 + n) * H + kq];
    }

    for (int s = 0; s < 24; s++) {
        __syncthreads();
        #pragma unroll
        for (int it = 0; it < 4; it++) {
            int idx = tid + it * 256;
            int m = idx >> 3, kq = (idx & 7) << 2;
            As[(kq+0)*ASTR + m] = pa[it].x;
            As[(kq+1)*ASTR + m] = pa[it].y;
            As[(kq+2)*ASTR + m] = pa[it].z;
            As[(kq+3)*ASTR + m] = pa[it].w;
        }
        #pragma unroll
        for (int it = 0; it < 3; it++) {
            int idx = tid + it * 256;
            int n = idx >> 3, kq = (idx & 7) << 2;
            Bs[(kq+0)*BSTR + n] = pb[it].x;
            Bs[(kq+1)*BSTR + n] = pb[it].y;
            Bs[(kq+2)*BSTR + n] = pb[it].z;
            Bs[(kq+3)*BSTR + n] = pb[it].w;
        }
        __syncthreads();

        if (s < 23) {
            const int k0 = (s + 1) * 32;
            #pragma unroll
            for (int it = 0; it < 4; it++) {
                int idx = tid + it * 256;
                int m = idx >> 3, kq = (idx & 7) << 2;
                pa[it] = *(const float4*)&x[(size_t)(m0 + m) * H + k0 + kq];
            }
            #pragma unroll
            for (int it = 0; it < 3; it++) {
                int idx = tid + it * 256;
                int n = idx >> 3, kq = (idx & 7) << 2;
                pb[it] = *(const float4*)&W[(size_t)(n0 + n) * H + k0 + kq];
            }
        }

        #pragma unroll 8
        for (int k = 0; k < 32; k++) {
            float2 arp[4];           // {a(2i), a(2i+1)} m-pairs (natural from LDS.128)
            *(float4*)&arp[0] = *(const float4*)&As[k*ASTR + ty*8];
            *(float4*)&arp[2] = *(const float4*)&As[k*ASTR + ty*8 + 4];
            float br[6];
            *(float2*)&br[0] = *(const float2*)&Bs[k*BSTR + tx*6];
            *(float2*)&br[2] = *(const float2*)&Bs[k*BSTR + tx*6 + 2];
            *(float2*)&br[4] = *(const float2*)&Bs[k*BSTR + tx*6 + 4];
            float2 brd[6];
            #pragma unroll
            for (int j = 0; j < 6; j++) brd[j] = make_float2(br[j], br[j]);
            #pragma unroll
            for (int ip = 0; ip < 4; ip++)
                #pragma unroll
                for (int j = 0; j < 6; j++)
                    acc[ip][j] = f2fma(arp[ip], brd[j], acc[ip][j]);
        }
    }

    #pragma unroll
    for (int ip = 0; ip < 4; ip++) {
        int m = m0 + ty*8 + 2*ip;
        #pragma unroll
        for (int j = 0; j < 6; j++) {
            int n = n0 + tx*6 + j;
            float bsv = bias[n];
            out[(size_t)m * H + n]       = acc[ip][j].x + bsv;
            out[(size_t)(m+1) * H + n]   = acc[ip][j].y + bsv;
        }
    }
}

// ---------------------------------------------------------------------------
// Kernel 2: attention with p=-2 distance scores.
// grid (S/64=6, NH=12, B=2), block 256.
// Phase 1: packed f32x2 over j, paired reciprocal over d
//   (1/a + 1/b = (a+b)/(a*b), one MUFU.RCP per 2 dims per lane).
// K tile stored NEGATED + transposed [d][j]: diff = q + (-k), sign dies in square.
// ---------------------------------------------------------------------------
#define QSTR 68    // qs / vs row stride (16B aligned)
#define KSTR 68    // ks_t row stride
#define SCW 385

__global__ __launch_bounds__(256) void attn_kernel()
{
    extern __shared__ float sm[];
    float* qs = sm;                       // [64][QSTR]  row-major Q
    float* ks = sm + 64*QSTR;             // [64][KSTR]  -K transposed [d][j]; later V row-major
    float* sc = sm + 2*64*QSTR;           // [64][SCW]   scores -> probs
    float* rowsum = sc + 64*SCW;          // 64

    const int tid = threadIdx.x;
    const int b = blockIdx.z, h = blockIdx.y;
    const int i0 = blockIdx.x * 64;

    const float* Qb = g_q + (size_t)(b*SQ)*H + h*DHEAD;
    const float* Kb = g_k + (size_t)(b*SQ)*H + h*DHEAD;
    const float* Vb = g_v + (size_t)(b*SQ)*H + h*DHEAD;

    // Load Q tile [64][64] row-major
    for (int idx = tid; idx < 64*16; idx += 256) {
        int i = idx >> 4, c4 = (idx & 15) << 2;
        float4 v = *(const float4*)&Qb[(size_t)(i0+i)*H + c4];
        *(float4*)&qs[i*QSTR + c4] = v;
    }

    const int tx = tid & 15, ty = tid >> 4;

    // ---- Phase 1: scores ----
    for (int jt = 0; jt < 6; jt++) {
        int j0 = jt * 64;
        __syncthreads();
        // -K tile transposed: ks[d][j]
        for (int idx = tid; idx < 64*16; idx += 256) {
            int j = idx >> 4, d4 = (idx & 15) << 2;
            float4 v = *(const float4*)&Kb[(size_t)(j0+j)*H + d4];
            ks[(d4+0)*KSTR + j] = -v.x;
            ks[(d4+1)*KSTR + j] = -v.y;
            ks[(d4+2)*KSTR + j] = -v.z;
            ks[(d4+3)*KSTR + j] = -v.w;
        }
        __syncthreads();

        float2 acc[4][2];   // [i][jpack], jpack over 2 adjacent j
        #pragma unroll
        for (int i = 0; i < 4; i++) { acc[i][0] = make_float2(0.f,0.f); acc[i][1] = make_float2(0.f,0.f); }

        #pragma unroll 4
        for (int d = 0; d < 64; d += 2) {
            float4 nk0 = *(const float4*)&ks[d*KSTR + tx*4];
            float4 nk1 = *(const float4*)&ks[(d+1)*KSTR + tx*4];
            float2 nk0p[2] = { make_float2(nk0.x, nk0.y), make_float2(nk0.z, nk0.w) };
            float2 nk1p[2] = { make_float2(nk1.x, nk1.y), make_float2(nk1.z, nk1.w) };
            #pragma unroll
            for (int i = 0; i < 4; i++) {
                float2 q = *(const float2*)&qs[(ty*4+i)*QSTR + d];
                float2 q0 = make_float2(q.x, q.x);
                float2 q1 = make_float2(q.y, q.y);
                #pragma unroll
                for (int jp = 0; jp < 2; jp++) {
                    float2 d0 = f2add(q0, nk0p[jp]);
                    float2 d1 = f2add(q1, nk1p[jp]);
                    float2 a  = f2mul(d0, d0);
                    float2 bb = f2mul(d1, d1);
                    float2 s  = f2add(a, bb);
                    float2 p  = f2mul(a, bb);
                    float2 r  = make_float2(frcp_approx(p.x), frcp_approx(p.y));
                    acc[i][jp] = f2fma(s, r, acc[i][jp]);
                }
            }
        }
        #pragma unroll
        for (int i = 0; i < 4; i++) {
            float* row = &sc[(ty*4+i)*SCW + j0 + tx*4];
            row[0] = -frsqrt_approx(fsqrt_approx(acc[i][0].x));
            row[1] = -frsqrt_approx(fsqrt_approx(acc[i][0].y));
            row[2] = -frsqrt_approx(fsqrt_approx(acc[i][1].x));
            row[3] = -frsqrt_approx(fsqrt_approx(acc[i][1].y));
        }
    }
    __syncthreads();

    // ---- Phase 2: softmax rows (store unnormalized probs + rowsum) ----
    {
        const int wid = tid >> 5, lane = tid & 31;
        for (int i = wid; i < 64; i += 8) {
            float m = -3.402823466e38f;
            for (int j = lane; j < SQ; j += 32) m = fmaxf(m, sc[i*SCW + j]);
            #pragma unroll
            for (int o = 16; o; o >>= 1) m = fmaxf(m, __shfl_xor_sync(0xffffffffu, m, o));
            float s = 0.f;
            for (int j = lane; j < SQ; j += 32) {
                float p = __expf(sc[i*SCW + j] - m);
                sc[i*SCW + j] = p;
                s += p;
            }
            #pragma unroll
            for (int o = 16; o; o >>= 1) s += __shfl_xor_sync(0xffffffffu, s, o);
            if (lane == 0) rowsum[i] = s;
        }
    }
    __syncthreads();

    // ---- Phase 3: ctx = P @ V ----  (V row-major in ks buffer, packed over d)
    float2 acc2[4][2];
    #pragma unroll
    for (int i = 0; i < 4; i++) { acc2[i][0] = make_float2(0.f,0.f); acc2[i][1] = make_float2(0.f,0.f); }

    for (int jt = 0; jt < 6; jt++) {
        int j0 = jt * 64;
        for (int idx = tid; idx < 64*16; idx += 256) {
            int j = idx >> 4, d4 = (idx & 15) << 2;
            float4 v = *(const float4*)&Vb[(size_t)(j0+j)*H + d4];
            *(float4*)&ks[j*QSTR + d4] = v;
        }
        __syncthreads();
        #pragma unroll 4
        for (int j = 0; j < 64; j++) {
            float4 vv4 = *(const float4*)&ks[j*QSTR + tx*4];
            float2 vp0 = make_float2(vv4.x, vv4.y);
            float2 vp1 = make_float2(vv4.z, vv4.w);
            #pragma unroll
            for (int i = 0; i < 4; i++) {
                float pvs = sc[(ty*4+i)*SCW + j0 + j];
                float2 pp = make_float2(pvs, pvs);
                acc2[i][0] = f2fma(pp, vp0, acc2[i][0]);
                acc2[i][1] = f2fma(pp, vp1, acc2[i][1]);
            }
        }
        __syncthreads();
    }

    #pragma unroll
    for (int i = 0; i < 4; i++) {
        float rs = frcp_approx(rowsum[ty*4 + i]);
        int row = i0 + ty*4 + i;
        float* op = &g_ctx[(size_t)(b*SQ + row)*H + h*DHEAD + tx*4];
        op[0] = acc2[i][0].x * rs;
        op[1] = acc2[i][0].y * rs;
        op[2] = acc2[i][1].x * rs;
        op[3] = acc2[i][1].y * rs;
    }
}

// ---------------------------------------------------------------------------
// Kernel 3: residual + LayerNorm. One block per row.
// ---------------------------------------------------------------------------
__global__ __launch_bounds__(256) void ln_kernel(
    const float* __restrict__ x, const float* __restrict__ gam,
    const float* __restrict__ bet, float* __restrict__ out)
{
    const int r = blockIdx.x;
    const float* xr = x + (size_t)r * H;
    const float* cr = g_ctx + (size_t)r * H;
    const int tid = threadIdx.x;

    __shared__ float redS[8], redQ[8];

    float y[3];
    float s = 0.f, ss = 0.f;
    #pragma unroll
    for (int k = 0; k < 3; k++) {
        int j = tid + k * 256;
        y[k] = xr[j] + cr[j];
        s += y[k];
        ss += y[k] * y[k];
    }
    #pragma unroll
    for (int o = 16; o; o >>= 1) {
        s  += __shfl_xor_sync(0xffffffffu, s, o);
        ss += __shfl_xor_sync(0xffffffffu, ss, o);
    }
    const int wid = tid >> 5, lane = tid & 31;
    if (lane == 0) { redS[wid] = s; redQ[wid] = ss; }
    __syncthreads();
    if (tid == 0) {
        float a = 0.f, b2 = 0.f;
        #pragma unroll
        for (int w = 0; w < 8; w++) { a += redS[w]; b2 += redQ[w]; }
        redS[0] = a; redQ[0] = b2;
    }
    __syncthreads();
    const float mu  = redS[0] * (1.f / (float)H);
    const float var = redQ[0] * (1.f / (float)H) - mu * mu;
    const float inv = rsqrtf(var + 1e-12f);

    #pragma unroll
    for (int k = 0; k < 3; k++) {
        int j = tid + k * 256;
        out[(size_t)r * H + j] = (y[k] - mu) * inv * gam[j] + bet[j];
    }
}

// ---------------------------------------------------------------------------
extern "C" void kernel_launch(void* const* d_in, const int* in_sizes, int n_in,
                              void* d_out, int out_size)
{
    const float* x   = (const float*)d_in[0];
    const float* Wq  = (const float*)d_in[1];
    const float* bq  = (const float*)d_in[2];
    const float* Wk  = (const float*)d_in[3];
    const float* bk  = (const float*)d_in[4];
    const float* Wv  = (const float*)d_in[5];
    const float* bv  = (const float*)d_in[6];
    const float* lng = (const float*)d_in[7];
    const float* lnb = (const float*)d_in[8];
    float* out = (float*)d_out;

    // 1) fused QKV projection: grid (6 m-tiles, 24 n-tiles) = 144 CTAs
    qkv_gemm<<<dim3(6, 24), 256>>>(x, Wq, bq, Wk, bk, Wv, bv);

    // 2) attention
    size_t smem = (size_t)(2*64*QSTR + 64*SCW + 64) * sizeof(float);   // ~130.5 KB
    cudaFuncSetAttribute(attn_kernel, cudaFuncAttributeMaxDynamicSharedMemorySize, (int)smem);
    attn_kernel<<<dim3(6, NHEADS, BB), 256, smem>>>();

    // 3) residual + LayerNorm
    ln_kernel<<<BS, 256>>>(x, lng, lnb, out);
}

// round 6
// speedup vs baseline: 1.4347x; 1.1016x over previous
#include <cuda_runtime.h>

#define H 768
#define SQ 384
#define BB 2
#define NHEADS 12
#define DHEAD 64
#define BS (BB*SQ)   // 768 rows total

// Scratch (allocation-free rule: __device__ globals)
__device__ float g_q[BS*H];
__device__ float g_k[BS*H];
__device__ float g_v[BS*H];
__device__ float g_ctx[BS*H];

__device__ __forceinline__ float frcp_approx(float x){ float r; asm("rcp.approx.ftz.f32 %0, %1;" : "=f"(r) : "f"(x)); return r; }
__device__ __forceinline__ float fsqrt_approx(float x){ float r; asm("sqrt.approx.f32 %0, %1;" : "=f"(r) : "f"(x)); return r; }
__device__ __forceinline__ float frsqrt_approx(float x){ float r; asm("rsqrt.approx.f32 %0, %1;" : "=f"(r) : "f"(x)); return r; }

// ---- packed fp32x2 ops (Blackwell FFMA2 path; IEEE fp32 per lane) ----
union F2U { float2 f; unsigned long long u; };
__device__ __forceinline__ float2 f2fma(float2 a, float2 b, float2 c){
    F2U A, Bv, C, R; A.f = a; Bv.f = b; C.f = c;
    asm("fma.rn.f32x2 %0, %1, %2, %3;" : "=l"(R.u) : "l"(A.u), "l"(Bv.u), "l"(C.u));
    return R.f;
}
__device__ __forceinline__ float2 f2add(float2 a, float2 b){
    F2U A, Bv, R; A.f = a; Bv.f = b;
    asm("add.rn.f32x2 %0, %1, %2;" : "=l"(R.u) : "l"(A.u), "l"(Bv.u));
    return R.f;
}
__device__ __forceinline__ float2 f2mul(float2 a, float2 b){
    F2U A, Bv, R; A.f = a; Bv.f = b;
    asm("mul.rn.f32x2 %0, %1, %2;" : "=l"(R.u) : "l"(A.u), "l"(Bv.u));
    return R.f;
}

// ---------------------------------------------------------------------------
// Kernel 1: fused QKV projection as one 768 x 2304 GEMM.
// CTA tile 128(M) x 96(N), k-slab 32, 256 threads, 8x6 register tile (f32x2
// packed over M pairs). DOUBLE-BUFFERED dynamic smem (59392 B): one
// __syncthreads per slab, STS of slab s+1 overlaps compute of slab s.
// grid (6, 24) = 144 CTAs = one wave on 148 SMs.
// ---------------------------------------------------------------------------
#define ASTR 132   // As row stride (padded, 16B-aligned)
#define BSTR 100   // Bs row stride (padded, 8B-aligned)
#define ABUF (32*ASTR)   // 4224 floats per A buffer
#define BBUF (32*BSTR)   // 3200 floats per B buffer
#define GEMM_SMEM ((2*(ABUF+BBUF))*sizeof(float))   // 59392 bytes

__global__ __launch_bounds__(256) void qkv_gemm(
    const float* __restrict__ x,
    const float* __restrict__ Wq, const float* __restrict__ bq,
    const float* __restrict__ Wk, const float* __restrict__ bk,
    const float* __restrict__ Wv, const float* __restrict__ bv)
{
    extern __shared__ float gsm[];
    float* As0 = gsm;                    // [32*ASTR]
    float* As1 = gsm + ABUF;             // [32*ASTR]
    float* Bs0 = gsm + 2*ABUF;           // [32*BSTR]
    float* Bs1 = gsm + 2*ABUF + BBUF;    // [32*BSTR]

    const int tid = threadIdx.x;
    const int m0 = blockIdx.x * 128;
    const int ng0 = blockIdx.y * 96;           // global n in [0, 2304)
    const int z  = ng0 / 768;                  // which projection
    const int n0 = ng0 - z * 768;              // local n

    const float* W; const float* bias; float* out;
    if (z == 0)      { W = Wq; bias = bq; out = g_q; }
    else if (z == 1) { W = Wk; bias = bk; out = g_k; }
    else             { W = Wv; bias = bv; out = g_v; }

    const int tx = tid & 15;     // n group: 6 cols each
    const int ty = tid >> 4;     // m group: 8 rows each

    float2 acc[4][6];            // packed over m pairs
    #pragma unroll
    for (int i = 0; i < 4; i++)
        #pragma unroll
        for (int j = 0; j < 6; j++) acc[i][j] = make_float2(0.f, 0.f);

    float4 pa[4], pb[3];

    // per-thread load coords (reused every slab)
    const int amr[4] = { (tid+0*256)>>3, (tid+1*256)>>3, (tid+2*256)>>3, (tid+3*256)>>3 };
    const int akq    = (tid & 7) << 2;

    // ---- prefetch slab 0 ----
    #pragma unroll
    for (int it = 0; it < 4; it++)
        pa[it] = *(const float4*)&x[(size_t)(m0 + amr[it]) * H + akq];
    #pragma unroll
    for (int it = 0; it < 3; it++)
        pb[it] = *(const float4*)&W[(size_t)(n0 + amr[it]) * H + akq];

    for (int s = 0; s < 24; s++) {
        float* As = (s & 1) ? As1 : As0;
        float* Bs = (s & 1) ? Bs1 : Bs0;
        // store prefetched slab s into buffer (transposed [k][m]/[k][n])
        #pragma unroll
        for (int it = 0; it < 4; it++) {
            int m = amr[it];
            As[(akq+0)*ASTR + m] = pa[it].x;
            As[(akq+1)*ASTR + m] = pa[it].y;
            As[(akq+2)*ASTR + m] = pa[it].z;
            As[(akq+3)*ASTR + m] = pa[it].w;
        }
        #pragma unroll
        for (int it = 0; it < 3; it++) {
            int n = amr[it];
            Bs[(akq+0)*BSTR + n] = pb[it].x;
            Bs[(akq+1)*BSTR + n] = pb[it].y;
            Bs[(akq+2)*BSTR + n] = pb[it].z;
            Bs[(akq+3)*BSTR + n] = pb[it].w;
        }
        __syncthreads();   // slab s visible; also: all warps finished compute(s-1)

        // prefetch slab s+1 from gmem while computing slab s
        if (s < 23) {
            const int k0 = (s + 1) * 32;
            #pragma unroll
            for (int it = 0; it < 4; it++)
                pa[it] = *(const float4*)&x[(size_t)(m0 + amr[it]) * H + k0 + akq];
            #pragma unroll
            for (int it = 0; it < 3; it++)
                pb[it] = *(const float4*)&W[(size_t)(n0 + amr[it]) * H + k0 + akq];
        }

        #pragma unroll 8
        for (int k = 0; k < 32; k++) {
            float2 arp[4];
            *(float4*)&arp[0] = *(const float4*)&As[k*ASTR + ty*8];
            *(float4*)&arp[2] = *(const float4*)&As[k*ASTR + ty*8 + 4];
            float br[6];
            *(float2*)&br[0] = *(const float2*)&Bs[k*BSTR + tx*6];
            *(float2*)&br[2] = *(const float2*)&Bs[k*BSTR + tx*6 + 2];
            *(float2*)&br[4] = *(const float2*)&Bs[k*BSTR + tx*6 + 4];
            float2 brd[6];
            #pragma unroll
            for (int j = 0; j < 6; j++) brd[j] = make_float2(br[j], br[j]);
            #pragma unroll
            for (int ip = 0; ip < 4; ip++)
                #pragma unroll
                for (int j = 0; j < 6; j++)
                    acc[ip][j] = f2fma(arp[ip], brd[j], acc[ip][j]);
        }
    }

    #pragma unroll
    for (int ip = 0; ip < 4; ip++) {
        int m = m0 + ty*8 + 2*ip;
        #pragma unroll
        for (int j = 0; j < 6; j++) {
            int n = n0 + tx*6 + j;
            float bsv = bias[n];
            out[(size_t)m * H + n]       = acc[ip][j].x + bsv;
            out[(size_t)(m+1) * H + n]   = acc[ip][j].y + bsv;
        }
    }
}

// ---------------------------------------------------------------------------
// Kernel 2: attention with p=-2 distance scores.
// grid (6, 12, 2), block 512 (16 warps -> 4/SMSP for latency hiding).
// 4-way reciprocal pairing: 1/a+1/b+1/c+1/e = ((a+b)ce + (c+e)ab)/(abce)
//   -> one MUFU.RCP per 4 dims per element.
// Underflow guard: Q,K scaled by 4 in smem (squares x16, products x65536);
//   compensated exactly: pm2 = 16*acc -> score = -0.5 * acc^(-1/4).
// K stored negated+transposed [d][j]: diff = q + (-k).
// ---------------------------------------------------------------------------
#define QSTR 68    // qs / vs row stride (16B aligned)
#define KSTR 68    // ks_t row stride
#define SCW 385

__global__ __launch_bounds__(512) void attn_kernel()
{
    extern __shared__ float sm[];
    float* qs = sm;                       // [64][QSTR]  row-major 4*Q
    float* ks = sm + 64*QSTR;             // [64][KSTR]  -4*K transposed [d][j]; later V row-major
    float* sc = sm + 2*64*QSTR;           // [64][SCW]   scores -> probs
    float* rowsum = sc + 64*SCW;          // 64

    const int tid = threadIdx.x;
    const int b = blockIdx.z, h = blockIdx.y;
    const int i0 = blockIdx.x * 64;

    const float* Qb = g_q + (size_t)(b*SQ)*H + h*DHEAD;
    const float* Kb = g_k + (size_t)(b*SQ)*H + h*DHEAD;
    const float* Vb = g_v + (size_t)(b*SQ)*H + h*DHEAD;

    // Load Q tile [64][64] row-major, scaled by 4
    for (int idx = tid; idx < 64*16; idx += 512) {
        int i = idx >> 4, c4 = (idx & 15) << 2;
        float4 v = *(const float4*)&Qb[(size_t)(i0+i)*H + c4];
        v.x *= 4.f; v.y *= 4.f; v.z *= 4.f; v.w *= 4.f;
        *(float4*)&qs[i*QSTR + c4] = v;
    }

    const int tx = tid & 31;   // j group: 2 cols each (64 j)
    const int ty = tid >> 5;   // i group: 4 rows each (64 i)

    // ---- Phase 1: scores ----
    for (int jt = 0; jt < 6; jt++) {
        int j0 = jt * 64;
        __syncthreads();
        // -4*K tile transposed: ks[d][j]
        for (int idx = tid; idx < 64*16; idx += 512) {
            int j = idx >> 4, d4 = (idx & 15) << 2;
            float4 v = *(const float4*)&Kb[(size_t)(j0+j)*H + d4];
            ks[(d4+0)*KSTR + j] = -4.f*v.x;
            ks[(d4+1)*KSTR + j] = -4.f*v.y;
            ks[(d4+2)*KSTR + j] = -4.f*v.z;
            ks[(d4+3)*KSTR + j] = -4.f*v.w;
        }
        __syncthreads();

        float2 acc[4];   // [i], f32x2 over 2 adjacent j
        #pragma unroll
        for (int i = 0; i < 4; i++) acc[i] = make_float2(0.f, 0.f);

        #pragma unroll 4
        for (int d = 0; d < 64; d += 4) {
            float2 nk0 = *(const float2*)&ks[(d+0)*KSTR + tx*2];
            float2 nk1 = *(const float2*)&ks[(d+1)*KSTR + tx*2];
            float2 nk2 = *(const float2*)&ks[(d+2)*KSTR + tx*2];
            float2 nk3 = *(const float2*)&ks[(d+3)*KSTR + tx*2];
            #pragma unroll
            for (int i = 0; i < 4; i++) {
                float4 q = *(const float4*)&qs[(ty*4+i)*QSTR + d];
                float2 d0 = f2add(make_float2(q.x, q.x), nk0);
                float2 d1 = f2add(make_float2(q.y, q.y), nk1);
                float2 d2 = f2add(make_float2(q.z, q.z), nk2);
                float2 d3 = f2add(make_float2(q.w, q.w), nk3);
                float2 a  = f2mul(d0, d0);
                float2 bq2 = f2mul(d1, d1);
                float2 c  = f2mul(d2, d2);
                float2 e  = f2mul(d3, d3);
                float2 ab = f2mul(a, bq2);
                float2 ce = f2mul(c, e);
                float2 sab = f2add(a, bq2);
                float2 sce = f2add(c, e);
                float2 num = f2fma(sab, ce, f2mul(sce, ab));
                float2 den = f2mul(ab, ce);
                float2 r   = make_float2(frcp_approx(den.x), frcp_approx(den.y));
                acc[i] = f2fma(num, r, acc[i]);
            }
        }
        // score = -(16*acc)^(-1/4) = -0.5 * acc^(-1/4)
        #pragma unroll
        for (int i = 0; i < 4; i++) {
            float* row = &sc[(ty*4+i)*SCW + j0 + tx*2];
            row[0] = -0.5f * frsqrt_approx(fsqrt_approx(acc[i].x));
            row[1] = -0.5f * frsqrt_approx(fsqrt_approx(acc[i].y));
        }
    }
    __syncthreads();

    // ---- Phase 2: softmax rows (store unnormalized probs + rowsum) ----
    {
        const int wid = tid >> 5, lane = tid & 31;
        for (int i = wid; i < 64; i += 16) {
            float m = -3.402823466e38f;
            for (int j = lane; j < SQ; j += 32) m = fmaxf(m, sc[i*SCW + j]);
            #pragma unroll
            for (int o = 16; o; o >>= 1) m = fmaxf(m, __shfl_xor_sync(0xffffffffu, m, o));
            float s = 0.f;
            for (int j = lane; j < SQ; j += 32) {
                float p = __expf(sc[i*SCW + j] - m);
                sc[i*SCW + j] = p;
                s += p;
            }
            #pragma unroll
            for (int o = 16; o; o >>= 1) s += __shfl_xor_sync(0xffffffffu, s, o);
            if (lane == 0) rowsum[i] = s;
        }
    }
    __syncthreads();

    // ---- Phase 3: ctx = P @ V ----  (V row-major in ks buffer; d split 2/thread)
    float2 acc2[4];
    #pragma unroll
    for (int i = 0; i < 4; i++) acc2[i] = make_float2(0.f, 0.f);

    for (int jt = 0; jt < 6; jt++) {
        int j0 = jt * 64;
        for (int idx = tid; idx < 64*16; idx += 512) {
            int j = idx >> 4, d4 = (idx & 15) << 2;
            float4 v = *(const float4*)&Vb[(size_t)(j0+j)*H + d4];
            *(float4*)&ks[j*QSTR + d4] = v;
        }
        __syncthreads();
        #pragma unroll 4
        for (int j = 0; j < 64; j++) {
            float2 vv = *(const float2*)&ks[j*QSTR + tx*2];
            #pragma unroll
            for (int i = 0; i < 4; i++) {
                float pvs = sc[(ty*4+i)*SCW + j0 + j];
                acc2[i] = f2fma(make_float2(pvs, pvs), vv, acc2[i]);
            }
        }
        __syncthreads();
    }

    #pragma unroll
    for (int i = 0; i < 4; i++) {
        float rs = frcp_approx(rowsum[ty*4 + i]);
        int row = i0 + ty*4 + i;
        float* op = &g_ctx[(size_t)(b*SQ + row)*H + h*DHEAD + tx*2];
        op[0] = acc2[i].x * rs;
        op[1] = acc2[i].y * rs;
    }
}

// ---------------------------------------------------------------------------
// Kernel 3: residual + LayerNorm. One block per row.
// ---------------------------------------------------------------------------
__global__ __launch_bounds__(256) void ln_kernel(
    const float* __restrict__ x, const float* __restrict__ gam,
    const float* __restrict__ bet, float* __restrict__ out)
{
    const int r = blockIdx.x;
    const float* xr = x + (size_t)r * H;
    const float* cr = g_ctx + (size_t)r * H;
    const int tid = threadIdx.x;

    __shared__ float redS[8], redQ[8];

    float y[3];
    float s = 0.f, ss = 0.f;
    #pragma unroll
    for (int k = 0; k < 3; k++) {
        int j = tid + k * 256;
        y[k] = xr[j] + cr[j];
        s += y[k];
        ss += y[k] * y[k];
    }
    #pragma unroll
    for (int o = 16; o; o >>= 1) {
        s  += __shfl_xor_sync(0xffffffffu, s, o);
        ss += __shfl_xor_sync(0xffffffffu, ss, o);
    }
    const int wid = tid >> 5, lane = tid & 31;
    if (lane == 0) { redS[wid] = s; redQ[wid] = ss; }
    __syncthreads();
    if (tid == 0) {
        float a = 0.f, b2 = 0.f;
        #pragma unroll
        for (int w = 0; w < 8; w++) { a += redS[w]; b2 += redQ[w]; }
        redS[0] = a; redQ[0] = b2;
    }
    __syncthreads();
    const float mu  = redS[0] * (1.f / (float)H);
    const float var = redQ[0] * (1.f / (float)H) - mu * mu;
    const float inv = rsqrtf(var + 1e-12f);

    #pragma unroll
    for (int k = 0; k < 3; k++) {
        int j = tid + k * 256;
        out[(size_t)r * H + j] = (y[k] - mu) * inv * gam[j] + bet[j];
    }
}

// ---------------------------------------------------------------------------
extern "C" void kernel_launch(void* const* d_in, const int* in_sizes, int n_in,
                              void* d_out, int out_size)
{
    const float* x   = (const float*)d_in[0];
    const float* Wq  = (const float*)d_in[1];
    const float* bq  = (const float*)d_in[2];
    const float* Wk  = (const float*)d_in[3];
    const float* bk  = (const float*)d_in[4];
    const float* Wv  = (const float*)d_in[5];
    const float* bv  = (const float*)d_in[6];
    const float* lng = (const float*)d_in[7];
    const float* lnb = (const float*)d_in[8];
    float* out = (float*)d_out;

    // 1) fused QKV projection: grid (6 m-tiles, 24 n-tiles) = 144 CTAs
    cudaFuncSetAttribute(qkv_gemm, cudaFuncAttributeMaxDynamicSharedMemorySize, (int)GEMM_SMEM);
    qkv_gemm<<<dim3(6, 24), 256, GEMM_SMEM>>>(x, Wq, bq, Wk, bk, Wv, bv);

    // 2) attention
    size_t smem = (size_t)(2*64*QSTR + 64*SCW + 64) * sizeof(float);   // ~130.5 KB
    cudaFuncSetAttribute(attn_kernel, cudaFuncAttributeMaxDynamicSharedMemorySize, (int)smem);
    attn_kernel<<<dim3(6, NHEADS, BB), 512, smem>>>();

    // 3) residual + LayerNorm
    ln_kernel<<<BS, 256>>>(x, lng, lnb, out);
}

// round 8
// speedup vs baseline: 1.8187x; 1.2677x over previous
#include <cuda_runtime.h>
#include <cuda_bf16.h>
#include <cstdint>

#define H 768
#define SQ 384
#define BB 2
#define NHEADS 12
#define DHEAD 64
#define BS (BB*SQ)   // 768 rows total

// Scratch (allocation-free rule: __device__ globals)
__device__ float g_q[BS*H];
__device__ float g_k[BS*H];
__device__ float g_v[BS*H];
__device__ float g_ctx[BS*H];

__device__ __forceinline__ float frcp_approx(float x){ float r; asm("rcp.approx.ftz.f32 %0, %1;" : "=f"(r) : "f"(x)); return r; }
__device__ __forceinline__ float fsqrt_approx(float x){ float r; asm("sqrt.approx.f32 %0, %1;" : "=f"(r) : "f"(x)); return r; }
__device__ __forceinline__ float frsqrt_approx(float x){ float r; asm("rsqrt.approx.f32 %0, %1;" : "=f"(r) : "f"(x)); return r; }

// ---- packed fp32x2 ops ----
union F2U { float2 f; unsigned long long u; };
__device__ __forceinline__ float2 f2fma(float2 a, float2 b, float2 c){
    F2U A, Bv, C, R; A.f = a; Bv.f = b; C.f = c;
    asm("fma.rn.f32x2 %0, %1, %2, %3;" : "=l"(R.u) : "l"(A.u), "l"(Bv.u), "l"(C.u));
    return R.f;
}
__device__ __forceinline__ float2 f2add(float2 a, float2 b){
    F2U A, Bv, R; A.f = a; Bv.f = b;
    asm("add.rn.f32x2 %0, %1, %2;" : "=l"(R.u) : "l"(A.u), "l"(Bv.u));
    return R.f;
}
__device__ __forceinline__ float2 f2mul(float2 a, float2 b){
    F2U A, Bv, R; A.f = a; Bv.f = b;
    asm("mul.rn.f32x2 %0, %1, %2;" : "=l"(R.u) : "l"(A.u), "l"(Bv.u));
    return R.f;
}

// ---- warp-level bf16 MMA (m16n8k16, HMMA path, supported on base sm_100) ----
__device__ __forceinline__ void mma16816(float* d,
    uint32_t a0, uint32_t a1, uint32_t a2, uint32_t a3,
    uint32_t b0, uint32_t b1)
{
    asm("mma.sync.aligned.m16n8k16.row.col.f32.bf16.bf16.f32 "
        "{%0,%1,%2,%3}, {%4,%5,%6,%7}, {%8,%9}, {%0,%1,%2,%3};"
        : "+f"(d[0]), "+f"(d[1]), "+f"(d[2]), "+f"(d[3])
        : "r"(a0), "r"(a1), "r"(a2), "r"(a3), "r"(b0), "r"(b1));
}

// split fp32 -> (hi, lo) bf16 pair, packed as bf16x2 words
__device__ __forceinline__ void split2(float f0, float f1, uint32_t& hw, uint32_t& lw){
    __nv_bfloat16 h0 = __float2bfloat16_rn(f0);
    __nv_bfloat16 h1 = __float2bfloat16_rn(f1);
    __nv_bfloat16 l0 = __float2bfloat16_rn(f0 - __bfloat162float(h0));
    __nv_bfloat16 l1 = __float2bfloat16_rn(f1 - __bfloat162float(h1));
    hw = (uint32_t)*(uint16_t*)&h0 | ((uint32_t)*(uint16_t*)&h1 << 16);
    lw = (uint32_t)*(uint16_t*)&l0 | ((uint32_t)*(uint16_t*)&l1 << 16);
}

// ---------------------------------------------------------------------------
// Kernel 1: fused QKV projection on tensor cores (bf16 2-split, 3 passes).
// out[m, ng] = sum_k x[m,k]*W[z][n,k] + b[z][n]
// CTA tile 128(M) x 96(N); 8 warps as 4(M) x 2(N) -> warp tile 32x48.
// K processed in slabs of 32 (2 k16 steps). grid (6, 24) = 144 CTAs = 1 wave.
// Smem (bf16, row stride 40): A_hi|A_lo [128][40], B_hi|B_lo [96][40].
// ---------------------------------------------------------------------------
#define RSTR 40                   // bf16 row stride (20 words) -> conflict-free frags
#define OF_AH 0
#define OF_AL (128*RSTR)          // 5120
#define OF_BH (2*128*RSTR)        // 10240
#define OF_BL (2*128*RSTR + 96*RSTR)   // 14080
#define SM_BF16 (2*128*RSTR + 2*96*RSTR) // 17920 bf16 = 35840 B (static ok)

__global__ __launch_bounds__(256) void qkv_mma(
    const float* __restrict__ x,
    const float* __restrict__ Wq, const float* __restrict__ bq,
    const float* __restrict__ Wk, const float* __restrict__ bk,
    const float* __restrict__ Wv, const float* __restrict__ bv)
{
    __shared__ __nv_bfloat16 smb[SM_BF16];
    uint32_t* smw = (uint32_t*)smb;      // word view (bf16x2)

    const int tid = threadIdx.x;
    const int wid = tid >> 5, lane = tid & 31;
    const int gid = lane >> 2, tg = lane & 3;
    const int warp_m = wid >> 1, warp_n = wid & 1;

    const int m0 = blockIdx.x * 128;
    const int ntile = blockIdx.y;            // 0..23
    const int z = ntile >> 3;
    const int n0 = (ntile & 7) * 96;

    const float* W; const float* bias; float* out;
    if (z == 0)      { W = Wq; bias = bq; out = g_q; }
    else if (z == 1) { W = Wk; bias = bk; out = g_k; }
    else             { W = Wv; bias = bv; out = g_v; }

    float acc[2][6][4];
    #pragma unroll
    for (int mi = 0; mi < 2; mi++)
        #pragma unroll
        for (int j = 0; j < 6; j++)
            #pragma unroll
            for (int e = 0; e < 4; e++) acc[mi][j][e] = 0.f;

    for (int s = 0; s < 24; s++) {
        const int k0g = s * 32;
        __syncthreads();   // previous slab consumed
        // ---- A tile 128x32: 1024 float4 segs -> 4/thread ----
        #pragma unroll
        for (int it = 0; it < 4; it++) {
            int sg = tid + it * 256;
            int r = sg >> 3, q = sg & 7;
            float4 v = *(const float4*)&x[(size_t)(m0 + r) * H + k0g + q * 4];
            uint32_t h0, l0, h1, l1;
            split2(v.x, v.y, h0, l0);
            split2(v.z, v.w, h1, l1);
            int wo = r * (RSTR/2) + q * 2;
            *(uint2*)&smw[OF_AH/2 + wo] = make_uint2(h0, h1);
            *(uint2*)&smw[OF_AL/2 + wo] = make_uint2(l0, l1);
        }
        // ---- B tile 96x32: 768 segs -> 3/thread ----
        #pragma unroll
        for (int it = 0; it < 3; it++) {
            int sg = tid + it * 256;
            int r = sg >> 3, q = sg & 7;
            float4 v = *(const float4*)&W[(size_t)(n0 + r) * H + k0g + q * 4];
            uint32_t h0, l0, h1, l1;
            split2(v.x, v.y, h0, l0);
            split2(v.z, v.w, h1, l1);
            int wo = r * (RSTR/2) + q * 2;
            *(uint2*)&smw[OF_BH/2 + wo] = make_uint2(h0, h1);
            *(uint2*)&smw[OF_BL/2 + wo] = make_uint2(l0, l1);
        }
        __syncthreads();

        #pragma unroll
        for (int ks = 0; ks < 2; ks++) {
            const int kw = ks * 8;           // word offset of this k16 step
            // A fragments (hi & lo) for 2 m16 tiles
            uint32_t Ah[2][4], Al[2][4];
            #pragma unroll
            for (int mi = 0; mi < 2; mi++) {
                int r0 = warp_m * 32 + mi * 16 + gid;
                int base0 = r0 * (RSTR/2) + kw + tg;
                int base1 = (r0 + 8) * (RSTR/2) + kw + tg;
                Ah[mi][0] = smw[OF_AH/2 + base0];
                Ah[mi][1] = smw[OF_AH/2 + base1];
                Ah[mi][2] = smw[OF_AH/2 + base0 + 4];
                Ah[mi][3] = smw[OF_AH/2 + base1 + 4];
                Al[mi][0] = smw[OF_AL/2 + base0];
                Al[mi][1] = smw[OF_AL/2 + base1];
                Al[mi][2] = smw[OF_AL/2 + base0 + 4];
                Al[mi][3] = smw[OF_AL/2 + base1 + 4];
            }
            // B fragments (hi & lo) for 6 n8 tiles
            uint32_t Bh[6][2], Bl[6][2];
            #pragma unroll
            for (int j = 0; j < 6; j++) {
                int nr = warp_n * 48 + j * 8 + gid;
                int base = nr * (RSTR/2) + kw + tg;
                Bh[j][0] = smw[OF_BH/2 + base];
                Bh[j][1] = smw[OF_BH/2 + base + 4];
                Bl[j][0] = smw[OF_BL/2 + base];
                Bl[j][1] = smw[OF_BL/2 + base + 4];
            }
            #pragma unroll
            for (int mi = 0; mi < 2; mi++)
                #pragma unroll
                for (int j = 0; j < 6; j++) {
                    mma16816(acc[mi][j], Ah[mi][0],Ah[mi][1],Ah[mi][2],Ah[mi][3], Bh[j][0],Bh[j][1]);
                    mma16816(acc[mi][j], Ah[mi][0],Ah[mi][1],Ah[mi][2],Ah[mi][3], Bl[j][0],Bl[j][1]);
                    mma16816(acc[mi][j], Al[mi][0],Al[mi][1],Al[mi][2],Al[mi][3], Bh[j][0],Bh[j][1]);
                }
        }
    }

    // ---- epilogue: fragment layout c0,c1=(row gid, col 2tg,2tg+1), c2,c3=(row gid+8) ----
    #pragma unroll
    for (int mi = 0; mi < 2; mi++) {
        int r0 = m0 + warp_m * 32 + mi * 16 + gid;
        #pragma unroll
        for (int j = 0; j < 6; j++) {
            int nc = n0 + warp_n * 48 + j * 8 + tg * 2;
            float b0 = bias[nc], b1 = bias[nc + 1];
            *(float2*)&out[(size_t)r0 * H + nc]       = make_float2(acc[mi][j][0] + b0, acc[mi][j][1] + b1);
            *(float2*)&out[(size_t)(r0 + 8) * H + nc] = make_float2(acc[mi][j][2] + b0, acc[mi][j][3] + b1);
        }
    }
}

// ---------------------------------------------------------------------------
// Kernel 2: attention with p=-2 distance scores (unchanged, best known).
// ---------------------------------------------------------------------------
#define QSTR 68
#define KSTR 68
#define SCW 385

__global__ __launch_bounds__(512) void attn_kernel()
{
    extern __shared__ float sm[];
    float* qs = sm;
    float* ks = sm + 64*QSTR;
    float* sc = sm + 2*64*QSTR;
    float* rowsum = sc + 64*SCW;

    const int tid = threadIdx.x;
    const int b = blockIdx.z, h = blockIdx.y;
    const int i0 = blockIdx.x * 64;

    const float* Qb = g_q + (size_t)(b*SQ)*H + h*DHEAD;
    const float* Kb = g_k + (size_t)(b*SQ)*H + h*DHEAD;
    const float* Vb = g_v + (size_t)(b*SQ)*H + h*DHEAD;

    for (int idx = tid; idx < 64*16; idx += 512) {
        int i = idx >> 4, c4 = (idx & 15) << 2;
        float4 v = *(const float4*)&Qb[(size_t)(i0+i)*H + c4];
        v.x *= 4.f; v.y *= 4.f; v.z *= 4.f; v.w *= 4.f;
        *(float4*)&qs[i*QSTR + c4] = v;
    }

    const int tx = tid & 31;
    const int ty = tid >> 5;

    for (int jt = 0; jt < 6; jt++) {
        int j0 = jt * 64;
        __syncthreads();
        for (int idx = tid; idx < 64*16; idx += 512) {
            int j = idx >> 4, d4 = (idx & 15) << 2;
            float4 v = *(const float4*)&Kb[(size_t)(j0+j)*H + d4];
            ks[(d4+0)*KSTR + j] = -4.f*v.x;
            ks[(d4+1)*KSTR + j] = -4.f*v.y;
            ks[(d4+2)*KSTR + j] = -4.f*v.z;
            ks[(d4+3)*KSTR + j] = -4.f*v.w;
        }
        __syncthreads();

        float2 acc[4];
        #pragma unroll
        for (int i = 0; i < 4; i++) acc[i] = make_float2(0.f, 0.f);

        #pragma unroll 4
        for (int d = 0; d < 64; d += 4) {
            float2 nk0 = *(const float2*)&ks[(d+0)*KSTR + tx*2];
            float2 nk1 = *(const float2*)&ks[(d+1)*KSTR + tx*2];
            float2 nk2 = *(const float2*)&ks[(d+2)*KSTR + tx*2];
            float2 nk3 = *(const float2*)&ks[(d+3)*KSTR + tx*2];
            #pragma unroll
            for (int i = 0; i < 4; i++) {
                float4 q = *(const float4*)&qs[(ty*4+i)*QSTR + d];
                float2 d0 = f2add(make_float2(q.x, q.x), nk0);
                float2 d1 = f2add(make_float2(q.y, q.y), nk1);
                float2 d2 = f2add(make_float2(q.z, q.z), nk2);
                float2 d3 = f2add(make_float2(q.w, q.w), nk3);
                float2 a  = f2mul(d0, d0);
                float2 bq2 = f2mul(d1, d1);
                float2 c  = f2mul(d2, d2);
                float2 e  = f2mul(d3, d3);
                float2 ab = f2mul(a, bq2);
                float2 ce = f2mul(c, e);
                float2 sab = f2add(a, bq2);
                float2 sce = f2add(c, e);
                float2 num = f2fma(sab, ce, f2mul(sce, ab));
                float2 den = f2mul(ab, ce);
                float2 r   = make_float2(frcp_approx(den.x), frcp_approx(den.y));
                acc[i] = f2fma(num, r, acc[i]);
            }
        }
        #pragma unroll
        for (int i = 0; i < 4; i++) {
            float* row = &sc[(ty*4+i)*SCW + j0 + tx*2];
            row[0] = -0.5f * frsqrt_approx(fsqrt_approx(acc[i].x));
            row[1] = -0.5f * frsqrt_approx(fsqrt_approx(acc[i].y));
        }
    }
    __syncthreads();

    {
        const int wid = tid >> 5, lane = tid & 31;
        for (int i = wid; i < 64; i += 16) {
            float m = -3.402823466e38f;
            for (int j = lane; j < SQ; j += 32) m = fmaxf(m, sc[i*SCW + j]);
            #pragma unroll
            for (int o = 16; o; o >>= 1) m = fmaxf(m, __shfl_xor_sync(0xffffffffu, m, o));
            float s = 0.f;
            for (int j = lane; j < SQ; j += 32) {
                float p = __expf(sc[i*SCW + j] - m);
                sc[i*SCW + j] = p;
                s += p;
            }
            #pragma unroll
            for (int o = 16; o; o >>= 1) s += __shfl_xor_sync(0xffffffffu, s, o);
            if (lane == 0) rowsum[i] = s;
        }
    }
    __syncthreads();

    float2 acc2[4];
    #pragma unroll
    for (int i = 0; i < 4; i++) acc2[i] = make_float2(0.f, 0.f);

    for (int jt = 0; jt < 6; jt++) {
        int j0 = jt * 64;
        for (int idx = tid; idx < 64*16; idx += 512) {
            int j = idx >> 4, d4 = (idx & 15) << 2;
            float4 v = *(const float4*)&Vb[(size_t)(j0+j)*H + d4];
            *(float4*)&ks[j*QSTR + d4] = v;
        }
        __syncthreads();
        #pragma unroll 4
        for (int j = 0; j < 64; j++) {
            float2 vv = *(const float2*)&ks[j*QSTR + tx*2];
            #pragma unroll
            for (int i = 0; i < 4; i++) {
                float pvs = sc[(ty*4+i)*SCW + j0 + j];
                acc2[i] = f2fma(make_float2(pvs, pvs), vv, acc2[i]);
            }
        }
        __syncthreads();
    }

    #pragma unroll
    for (int i = 0; i < 4; i++) {
        float rs = frcp_approx(rowsum[ty*4 + i]);
        int row = i0 + ty*4 + i;
        float* op = &g_ctx[(size_t)(b*SQ + row)*H + h*DHEAD + tx*2];
        op[0] = acc2[i].x * rs;
        op[1] = acc2[i].y * rs;
    }
}

// ---------------------------------------------------------------------------
// Kernel 3: residual + LayerNorm.
// ---------------------------------------------------------------------------
__global__ __launch_bounds__(256) void ln_kernel(
    const float* __restrict__ x, const float* __restrict__ gam,
    const float* __restrict__ bet, float* __restrict__ out)
{
    const int r = blockIdx.x;
    const float* xr = x + (size_t)r * H;
    const float* cr = g_ctx + (size_t)r * H;
    const int tid = threadIdx.x;

    __shared__ float redS[8], redQ[8];

    float y[3];
    float s = 0.f, ss = 0.f;
    #pragma unroll
    for (int k = 0; k < 3; k++) {
        int j = tid + k * 256;
        y[k] = xr[j] + cr[j];
        s += y[k];
        ss += y[k] * y[k];
    }
    #pragma unroll
    for (int o = 16; o; o >>= 1) {
        s  += __shfl_xor_sync(0xffffffffu, s, o);
        ss += __shfl_xor_sync(0xffffffffu, ss, o);
    }
    const int wid = tid >> 5, lane = tid & 31;
    if (lane == 0) { redS[wid] = s; redQ[wid] = ss; }
    __syncthreads();
    if (tid == 0) {
        float a = 0.f, b2 = 0.f;
        #pragma unroll
        for (int w = 0; w < 8; w++) { a += redS[w]; b2 += redQ[w]; }
        redS[0] = a; redQ[0] = b2;
    }
    __syncthreads();
    const float mu  = redS[0] * (1.f / (float)H);
    const float var = redQ[0] * (1.f / (float)H) - mu * mu;
    const float inv = rsqrtf(var + 1e-12f);

    #pragma unroll
    for (int k = 0; k < 3; k++) {
        int j = tid + k * 256;
        out[(size_t)r * H + j] = (y[k] - mu) * inv * gam[j] + bet[j];
    }
}

// ---------------------------------------------------------------------------
extern "C" void kernel_launch(void* const* d_in, const int* in_sizes, int n_in,
                              void* d_out, int out_size)
{
    const float* x   = (const float*)d_in[0];
    const float* Wq  = (const float*)d_in[1];
    const float* bq  = (const float*)d_in[2];
    const float* Wk  = (const float*)d_in[3];
    const float* bk  = (const float*)d_in[4];
    const float* Wv  = (const float*)d_in[5];
    const float* bv  = (const float*)d_in[6];
    const float* lng = (const float*)d_in[7];
    const float* lnb = (const float*)d_in[8];
    float* out = (float*)d_out;

    // 1) fused QKV projection on tensor cores: grid (6, 24) = 144 CTAs
    qkv_mma<<<dim3(6, 24), 256>>>(x, Wq, bq, Wk, bk, Wv, bv);

    // 2) attention
    size_t smem = (size_t)(2*64*QSTR + 64*SCW + 64) * sizeof(float);
    cudaFuncSetAttribute(attn_kernel, cudaFuncAttributeMaxDynamicSharedMemorySize, (int)smem);
    attn_kernel<<<dim3(6, NHEADS, BB), 512, smem>>>();

    // 3) residual + LayerNorm
    ln_kernel<<<BS, 256>>>(x, lng, lnb, out);
}

// round 9
// speedup vs baseline: 1.8537x; 1.0192x over previous
#include <cuda_runtime.h>
#include <cuda_bf16.h>
#include <cstdint>

#define H 768
#define SQ 384
#define BB 2
#define NHEADS 12
#define DHEAD 64
#define BS (BB*SQ)   // 768 rows total

// Scratch (allocation-free rule: __device__ globals)
__device__ float g_q[BS*H];
__device__ float g_k[BS*H];
__device__ float g_v[BS*H];
__device__ float g_ctx[BS*H];

__device__ __forceinline__ float frcp_approx(float x){ float r; asm("rcp.approx.ftz.f32 %0, %1;" : "=f"(r) : "f"(x)); return r; }
__device__ __forceinline__ float fsqrt_approx(float x){ float r; asm("sqrt.approx.f32 %0, %1;" : "=f"(r) : "f"(x)); return r; }
__device__ __forceinline__ float frsqrt_approx(float x){ float r; asm("rsqrt.approx.f32 %0, %1;" : "=f"(r) : "f"(x)); return r; }

// ---- packed fp32x2 ops ----
union F2U { float2 f; unsigned long long u; };
__device__ __forceinline__ float2 f2fma(float2 a, float2 b, float2 c){
    F2U A, Bv, C, R; A.f = a; Bv.f = b; C.f = c;
    asm("fma.rn.f32x2 %0, %1, %2, %3;" : "=l"(R.u) : "l"(A.u), "l"(Bv.u), "l"(C.u));
    return R.f;
}
__device__ __forceinline__ float2 f2add(float2 a, float2 b){
    F2U A, Bv, R; A.f = a; Bv.f = b;
    asm("add.rn.f32x2 %0, %1, %2;" : "=l"(R.u) : "l"(A.u), "l"(Bv.u));
    return R.f;
}
__device__ __forceinline__ float2 f2mul(float2 a, float2 b){
    F2U A, Bv, R; A.f = a; Bv.f = b;
    asm("mul.rn.f32x2 %0, %1, %2;" : "=l"(R.u) : "l"(A.u), "l"(Bv.u));
    return R.f;
}

// ---- warp-level bf16 MMA (m16n8k16, HMMA path, supported on base sm_100) ----
__device__ __forceinline__ void mma16816(float* d,
    uint32_t a0, uint32_t a1, uint32_t a2, uint32_t a3,
    uint32_t b0, uint32_t b1)
{
    asm("mma.sync.aligned.m16n8k16.row.col.f32.bf16.bf16.f32 "
        "{%0,%1,%2,%3}, {%4,%5,%6,%7}, {%8,%9}, {%0,%1,%2,%3};"
        : "+f"(d[0]), "+f"(d[1]), "+f"(d[2]), "+f"(d[3])
        : "r"(a0), "r"(a1), "r"(a2), "r"(a3), "r"(b0), "r"(b1));
}

// split fp32 -> (hi, lo) bf16 pair, packed as bf16x2 words
__device__ __forceinline__ void split2(float f0, float f1, uint32_t& hw, uint32_t& lw){
    __nv_bfloat16 h0 = __float2bfloat16_rn(f0);
    __nv_bfloat16 h1 = __float2bfloat16_rn(f1);
    __nv_bfloat16 l0 = __float2bfloat16_rn(f0 - __bfloat162float(h0));
    __nv_bfloat16 l1 = __float2bfloat16_rn(f1 - __bfloat162float(h1));
    hw = (uint32_t)*(uint16_t*)&h0 | ((uint32_t)*(uint16_t*)&h1 << 16);
    lw = (uint32_t)*(uint16_t*)&l0 | ((uint32_t)*(uint16_t*)&l1 << 16);
}

// ---------------------------------------------------------------------------
// Kernel 1: fused QKV projection on tensor cores (bf16 2-split, 3 passes).
// CTA tile 128(M) x 96(N); 512 threads, 16 warps as 4(M) x 4(N) ->
// warp tile 32x24 (2 m16 x 3 n8). K slabs of 32 (2 k16 steps).
// Double-buffered smem + register prefetch: STS(s) ; sync ; LDG(s+1) ; MMA(s).
// grid (6, 24) = 144 CTAs = 1 wave.
// ---------------------------------------------------------------------------
#define RSTR 40                   // bf16 row stride -> conflict-free frags
#define OF_AH 0
#define OF_AL (128*RSTR)          // 5120 bf16
#define OF_BH (2*128*RSTR)        // 10240
#define OF_BL (2*128*RSTR + 96*RSTR)   // 14080
#define BUF_BF16 (2*128*RSTR + 2*96*RSTR)   // 17920 bf16 per buffer
#define QKV_SMEM (2*BUF_BF16*2)             // 71680 bytes

__global__ __launch_bounds__(512) void qkv_mma(
    const float* __restrict__ x,
    const float* __restrict__ Wq, const float* __restrict__ bq,
    const float* __restrict__ Wk, const float* __restrict__ bk,
    const float* __restrict__ Wv, const float* __restrict__ bv)
{
    extern __shared__ __nv_bfloat16 smb[];
    uint32_t* smw = (uint32_t*)smb;      // word view (bf16x2)

    const int tid = threadIdx.x;
    const int wid = tid >> 5, lane = tid & 31;
    const int gid = lane >> 2, tg = lane & 3;
    const int warp_m = wid >> 2, warp_n = wid & 3;

    const int m0 = blockIdx.x * 128;
    const int ntile = blockIdx.y;            // 0..23
    const int z = ntile >> 3;
    const int n0 = (ntile & 7) * 96;

    const float* W; const float* bias; float* out;
    if (z == 0)      { W = Wq; bias = bq; out = g_q; }
    else if (z == 1) { W = Wk; bias = bk; out = g_k; }
    else             { W = Wv; bias = bv; out = g_v; }

    float acc[2][3][4];
    #pragma unroll
    for (int mi = 0; mi < 2; mi++)
        #pragma unroll
        for (int j = 0; j < 3; j++)
            #pragma unroll
            for (int e = 0; e < 4; e++) acc[mi][j][e] = 0.f;

    // per-thread load coords: A has 1024 16B segs (2/thread), B has 768 (1.5/thread)
    const int rA0 = tid >> 3,          qA0 = tid & 7;          // seg tid
    const int rA1 = (tid + 512) >> 3,  qA1 = qA0;              // seg tid+512
    const int rB0 = rA0,               qB0 = qA0;              // seg tid (r<64? no r = tid>>3 < 64) -> B rows 0..63
    const int rB1 = rA1,               qB1 = qA0;              // seg tid+512 -> rows 64..95 for tid<256
    const bool hasB1 = (tid < 256);

    float4 pa0, pa1, pb0, pb1;

    // ---- prefetch slab 0 ----
    pa0 = *(const float4*)&x[(size_t)(m0 + rA0) * H + qA0 * 4];
    pa1 = *(const float4*)&x[(size_t)(m0 + rA1) * H + qA1 * 4];
    pb0 = *(const float4*)&W[(size_t)(n0 + rB0) * H + qB0 * 4];
    if (hasB1) pb1 = *(const float4*)&W[(size_t)(n0 + rB1) * H + qB1 * 4];

    for (int s = 0; s < 24; s++) {
        const uint32_t bofW = (s & 1) ? (BUF_BF16/2) : 0;   // word offset of buffer

        // ---- STS slab s (convert fp32 -> bf16 hi/lo) ----
        {
            uint32_t h0,l0,h1,l1;
            split2(pa0.x, pa0.y, h0, l0); split2(pa0.z, pa0.w, h1, l1);
            int wo = rA0 * (RSTR/2) + qA0 * 2;
            *(uint2*)&smw[bofW + OF_AH/2 + wo] = make_uint2(h0, h1);
            *(uint2*)&smw[bofW + OF_AL/2 + wo] = make_uint2(l0, l1);
            split2(pa1.x, pa1.y, h0, l0); split2(pa1.z, pa1.w, h1, l1);
            wo = rA1 * (RSTR/2) + qA1 * 2;
            *(uint2*)&smw[bofW + OF_AH/2 + wo] = make_uint2(h0, h1);
            *(uint2*)&smw[bofW + OF_AL/2 + wo] = make_uint2(l0, l1);
            split2(pb0.x, pb0.y, h0, l0); split2(pb0.z, pb0.w, h1, l1);
            wo = rB0 * (RSTR/2) + qB0 * 2;
            *(uint2*)&smw[bofW + OF_BH/2 + wo] = make_uint2(h0, h1);
            *(uint2*)&smw[bofW + OF_BL/2 + wo] = make_uint2(l0, l1);
            if (hasB1) {
                split2(pb1.x, pb1.y, h0, l0); split2(pb1.z, pb1.w, h1, l1);
                wo = rB1 * (RSTR/2) + qB1 * 2;
                *(uint2*)&smw[bofW + OF_BH/2 + wo] = make_uint2(h0, h1);
                *(uint2*)&smw[bofW + OF_BL/2 + wo] = make_uint2(l0, l1);
            }
        }
        __syncthreads();

        // ---- prefetch slab s+1 (overlaps MMA below) ----
        if (s < 23) {
            const int k0g = (s + 1) * 32;
            pa0 = *(const float4*)&x[(size_t)(m0 + rA0) * H + k0g + qA0 * 4];
            pa1 = *(const float4*)&x[(size_t)(m0 + rA1) * H + k0g + qA1 * 4];
            pb0 = *(const float4*)&W[(size_t)(n0 + rB0) * H + k0g + qB0 * 4];
            if (hasB1) pb1 = *(const float4*)&W[(size_t)(n0 + rB1) * H + k0g + qB1 * 4];
        }

        // ---- MMA slab s ----
        #pragma unroll
        for (int ks = 0; ks < 2; ks++) {
            const int kw = ks * 8;
            uint32_t Ah[2][4], Al[2][4];
            #pragma unroll
            for (int mi = 0; mi < 2; mi++) {
                int r0 = warp_m * 32 + mi * 16 + gid;
                int base0 = r0 * (RSTR/2) + kw + tg;
                int base1 = (r0 + 8) * (RSTR/2) + kw + tg;
                Ah[mi][0] = smw[bofW + OF_AH/2 + base0];
                Ah[mi][1] = smw[bofW + OF_AH/2 + base1];
                Ah[mi][2] = smw[bofW + OF_AH/2 + base0 + 4];
                Ah[mi][3] = smw[bofW + OF_AH/2 + base1 + 4];
                Al[mi][0] = smw[bofW + OF_AL/2 + base0];
                Al[mi][1] = smw[bofW + OF_AL/2 + base1];
                Al[mi][2] = smw[bofW + OF_AL/2 + base0 + 4];
                Al[mi][3] = smw[bofW + OF_AL/2 + base1 + 4];
            }
            uint32_t Bh[3][2], Bl[3][2];
            #pragma unroll
            for (int j = 0; j < 3; j++) {
                int nr = warp_n * 24 + j * 8 + gid;
                int base = nr * (RSTR/2) + kw + tg;
                Bh[j][0] = smw[bofW + OF_BH/2 + base];
                Bh[j][1] = smw[bofW + OF_BH/2 + base + 4];
                Bl[j][0] = smw[bofW + OF_BL/2 + base];
                Bl[j][1] = smw[bofW + OF_BL/2 + base + 4];
            }
            #pragma unroll
            for (int mi = 0; mi < 2; mi++)
                #pragma unroll
                for (int j = 0; j < 3; j++) {
                    mma16816(acc[mi][j], Ah[mi][0],Ah[mi][1],Ah[mi][2],Ah[mi][3], Bh[j][0],Bh[j][1]);
                    mma16816(acc[mi][j], Ah[mi][0],Ah[mi][1],Ah[mi][2],Ah[mi][3], Bl[j][0],Bl[j][1]);
                    mma16816(acc[mi][j], Al[mi][0],Al[mi][1],Al[mi][2],Al[mi][3], Bh[j][0],Bh[j][1]);
                }
        }
    }

    // ---- epilogue ----
    #pragma unroll
    for (int mi = 0; mi < 2; mi++) {
        int r0 = m0 + warp_m * 32 + mi * 16 + gid;
        #pragma unroll
        for (int j = 0; j < 3; j++) {
            int nc = n0 + warp_n * 24 + j * 8 + tg * 2;
            float b0 = bias[nc], b1 = bias[nc + 1];
            *(float2*)&out[(size_t)r0 * H + nc]       = make_float2(acc[mi][j][0] + b0, acc[mi][j][1] + b1);
            *(float2*)&out[(size_t)(r0 + 8) * H + nc] = make_float2(acc[mi][j][2] + b0, acc[mi][j][3] + b1);
        }
    }
}

// ---------------------------------------------------------------------------
// Kernel 2: attention with p=-2 distance scores (unchanged, best known).
// ---------------------------------------------------------------------------
#define QSTR 68
#define KSTR 68
#define SCW 385

__global__ __launch_bounds__(512) void attn_kernel()
{
    extern __shared__ float sm[];
    float* qs = sm;
    float* ks = sm + 64*QSTR;
    float* sc = sm + 2*64*QSTR;
    float* rowsum = sc + 64*SCW;

    const int tid = threadIdx.x;
    const int b = blockIdx.z, h = blockIdx.y;
    const int i0 = blockIdx.x * 64;

    const float* Qb = g_q + (size_t)(b*SQ)*H + h*DHEAD;
    const float* Kb = g_k + (size_t)(b*SQ)*H + h*DHEAD;
    const float* Vb = g_v + (size_t)(b*SQ)*H + h*DHEAD;

    for (int idx = tid; idx < 64*16; idx += 512) {
        int i = idx >> 4, c4 = (idx & 15) << 2;
        float4 v = *(const float4*)&Qb[(size_t)(i0+i)*H + c4];
        v.x *= 4.f; v.y *= 4.f; v.z *= 4.f; v.w *= 4.f;
        *(float4*)&qs[i*QSTR + c4] = v;
    }

    const int tx = tid & 31;
    const int ty = tid >> 5;

    for (int jt = 0; jt < 6; jt++) {
        int j0 = jt * 64;
        __syncthreads();
        for (int idx = tid; idx < 64*16; idx += 512) {
            int j = idx >> 4, d4 = (idx & 15) << 2;
            float4 v = *(const float4*)&Kb[(size_t)(j0+j)*H + d4];
            ks[(d4+0)*KSTR + j] = -4.f*v.x;
            ks[(d4+1)*KSTR + j] = -4.f*v.y;
            ks[(d4+2)*KSTR + j] = -4.f*v.z;
            ks[(d4+3)*KSTR + j] = -4.f*v.w;
        }
        __syncthreads();

        float2 acc[4];
        #pragma unroll
        for (int i = 0; i < 4; i++) acc[i] = make_float2(0.f, 0.f);

        #pragma unroll 4
        for (int d = 0; d < 64; d += 4) {
            float2 nk0 = *(const float2*)&ks[(d+0)*KSTR + tx*2];
            float2 nk1 = *(const float2*)&ks[(d+1)*KSTR + tx*2];
            float2 nk2 = *(const float2*)&ks[(d+2)*KSTR + tx*2];
            float2 nk3 = *(const float2*)&ks[(d+3)*KSTR + tx*2];
            #pragma unroll
            for (int i = 0; i < 4; i++) {
                float4 q = *(const float4*)&qs[(ty*4+i)*QSTR + d];
                float2 d0 = f2add(make_float2(q.x, q.x), nk0);
                float2 d1 = f2add(make_float2(q.y, q.y), nk1);
                float2 d2 = f2add(make_float2(q.z, q.z), nk2);
                float2 d3 = f2add(make_float2(q.w, q.w), nk3);
                float2 a  = f2mul(d0, d0);
                float2 bq2 = f2mul(d1, d1);
                float2 c  = f2mul(d2, d2);
                float2 e  = f2mul(d3, d3);
                float2 ab = f2mul(a, bq2);
                float2 ce = f2mul(c, e);
                float2 sab = f2add(a, bq2);
                float2 sce = f2add(c, e);
                float2 num = f2fma(sab, ce, f2mul(sce, ab));
                float2 den = f2mul(ab, ce);
                float2 r   = make_float2(frcp_approx(den.x), frcp_approx(den.y));
                acc[i] = f2fma(num, r, acc[i]);
            }
        }
        #pragma unroll
        for (int i = 0; i < 4; i++) {
            float* row = &sc[(ty*4+i)*SCW + j0 + tx*2];
            row[0] = -0.5f * frsqrt_approx(fsqrt_approx(acc[i].x));
            row[1] = -0.5f * frsqrt_approx(fsqrt_approx(acc[i].y));
        }
    }
    __syncthreads();

    {
        const int wid = tid >> 5, lane = tid & 31;
        for (int i = wid; i < 64; i += 16) {
            float m = -3.402823466e38f;
            for (int j = lane; j < SQ; j += 32) m = fmaxf(m, sc[i*SCW + j]);
            #pragma unroll
            for (int o = 16; o; o >>= 1) m = fmaxf(m, __shfl_xor_sync(0xffffffffu, m, o));
            float s = 0.f;
            for (int j = lane; j < SQ; j += 32) {
                float p = __expf(sc[i*SCW + j] - m);
                sc[i*SCW + j] = p;
                s += p;
            }
            #pragma unroll
            for (int o = 16; o; o >>= 1) s += __shfl_xor_sync(0xffffffffu, s, o);
            if (lane == 0) rowsum[i] = s;
        }
    }
    __syncthreads();

    float2 acc2[4];
    #pragma unroll
    for (int i = 0; i < 4; i++) acc2[i] = make_float2(0.f, 0.f);

    for (int jt = 0; jt < 6; jt++) {
        int j0 = jt * 64;
        for (int idx = tid; idx < 64*16; idx += 512) {
            int j = idx >> 4, d4 = (idx & 15) << 2;
            float4 v = *(const float4*)&Vb[(size_t)(j0+j)*H + d4];
            *(float4*)&ks[j*QSTR + d4] = v;
        }
        __syncthreads();
        #pragma unroll 4
        for (int j = 0; j < 64; j++) {
            float2 vv = *(const float2*)&ks[j*QSTR + tx*2];
            #pragma unroll
            for (int i = 0; i < 4; i++) {
                float pvs = sc[(ty*4+i)*SCW + j0 + j];
                acc2[i] = f2fma(make_float2(pvs, pvs), vv, acc2[i]);
            }
        }
        __syncthreads();
    }

    #pragma unroll
    for (int i = 0; i < 4; i++) {
        float rs = frcp_approx(rowsum[ty*4 + i]);
        int row = i0 + ty*4 + i;
        float* op = &g_ctx[(size_t)(b*SQ + row)*H + h*DHEAD + tx*2];
        op[0] = acc2[i].x * rs;
        op[1] = acc2[i].y * rs;
    }
}

// ---------------------------------------------------------------------------
// Kernel 3: residual + LayerNorm.
// ---------------------------------------------------------------------------
__global__ __launch_bounds__(256) void ln_kernel(
    const float* __restrict__ x, const float* __restrict__ gam,
    const float* __restrict__ bet, float* __restrict__ out)
{
    const int r = blockIdx.x;
    const float* xr = x + (size_t)r * H;
    const float* cr = g_ctx + (size_t)r * H;
    const int tid = threadIdx.x;

    __shared__ float redS[8], redQ[8];

    float y[3];
    float s = 0.f, ss = 0.f;
    #pragma unroll
    for (int k = 0; k < 3; k++) {
        int j = tid + k * 256;
        y[k] = xr[j] + cr[j];
        s += y[k];
        ss += y[k] * y[k];
    }
    #pragma unroll
    for (int o = 16; o; o >>= 1) {
        s  += __shfl_xor_sync(0xffffffffu, s, o);
        ss += __shfl_xor_sync(0xffffffffu, ss, o);
    }
    const int wid = tid >> 5, lane = tid & 31;
    if (lane == 0) { redS[wid] = s; redQ[wid] = ss; }
    __syncthreads();
    if (tid == 0) {
        float a = 0.f, b2 = 0.f;
        #pragma unroll
        for (int w = 0; w < 8; w++) { a += redS[w]; b2 += redQ[w]; }
        redS[0] = a; redQ[0] = b2;
    }
    __syncthreads();
    const float mu  = redS[0] * (1.f / (float)H);
    const float var = redQ[0] * (1.f / (float)H) - mu * mu;
    const float inv = rsqrtf(var + 1e-12f);

    #pragma unroll
    for (int k = 0; k < 3; k++) {
        int j = tid + k * 256;
        out[(size_t)r * H + j] = (y[k] - mu) * inv * gam[j] + bet[j];
    }
}

// ---------------------------------------------------------------------------
extern "C" void kernel_launch(void* const* d_in, const int* in_sizes, int n_in,
                              void* d_out, int out_size)
{
    const float* x   = (const float*)d_in[0];
    const float* Wq  = (const float*)d_in[1];
    const float* bq  = (const float*)d_in[2];
    const float* Wk  = (const float*)d_in[3];
    const float* bk  = (const float*)d_in[4];
    const float* Wv  = (const float*)d_in[5];
    const float* bv  = (const float*)d_in[6];
    const float* lng = (const float*)d_in[7];
    const float* lnb = (const float*)d_in[8];
    float* out = (float*)d_out;

    // 1) fused QKV projection on tensor cores: grid (6, 24) = 144 CTAs
    cudaFuncSetAttribute(qkv_mma, cudaFuncAttributeMaxDynamicSharedMemorySize, QKV_SMEM);
    qkv_mma<<<dim3(6, 24), 512, QKV_SMEM>>>(x, Wq, bq, Wk, bk, Wv, bv);

    // 2) attention
    size_t smem = (size_t)(2*64*QSTR + 64*SCW + 64) * sizeof(float);
    cudaFuncSetAttribute(attn_kernel, cudaFuncAttributeMaxDynamicSharedMemorySize, (int)smem);
    attn_kernel<<<dim3(6, NHEADS, BB), 512, smem>>>();

    // 3) residual + LayerNorm
    ln_kernel<<<BS, 256>>>(x, lng, lnb, out);
}

// round 11
// speedup vs baseline: 2.0502x; 1.1060x over previous
#include <cuda_runtime.h>
#include <cuda_bf16.h>
#include <cstdint>

#define H 768
#define SQ 384
#define BB 2
#define NHEADS 12
#define DHEAD 64
#define BS (BB*SQ)   // 768 rows total

// Scratch (allocation-free rule: __device__ globals)
__device__ float g_q[BS*H];
__device__ float g_k[BS*H];
__device__ float g_v[BS*H];
__device__ float g_ctx[BS*H];

__device__ __forceinline__ float frcp_approx(float x){ float r; asm("rcp.approx.ftz.f32 %0, %1;" : "=f"(r) : "f"(x)); return r; }
__device__ __forceinline__ float fsqrt_approx(float x){ float r; asm("sqrt.approx.f32 %0, %1;" : "=f"(r) : "f"(x)); return r; }
__device__ __forceinline__ float frsqrt_approx(float x){ float r; asm("rsqrt.approx.f32 %0, %1;" : "=f"(r) : "f"(x)); return r; }

// ---- packed fp32x2 ops ----
union F2U { float2 f; unsigned long long u; };
__device__ __forceinline__ float2 f2fma(float2 a, float2 b, float2 c){
    F2U A, Bv, C, R; A.f = a; Bv.f = b; C.f = c;
    asm("fma.rn.f32x2 %0, %1, %2, %3;" : "=l"(R.u) : "l"(A.u), "l"(Bv.u), "l"(C.u));
    return R.f;
}
__device__ __forceinline__ float2 f2add(float2 a, float2 b){
    F2U A, Bv, R; A.f = a; Bv.f = b;
    asm("add.rn.f32x2 %0, %1, %2;" : "=l"(R.u) : "l"(A.u), "l"(Bv.u));
    return R.f;
}
__device__ __forceinline__ float2 f2mul(float2 a, float2 b){
    F2U A, Bv, R; A.f = a; Bv.f = b;
    asm("mul.rn.f32x2 %0, %1, %2;" : "=l"(R.u) : "l"(A.u), "l"(Bv.u));
    return R.f;
}

// ---- warp-level bf16 MMA + ldmatrix (HMMA/LDSM path, base sm_100 OK) ----
__device__ __forceinline__ void mma16816(float* d,
    uint32_t a0, uint32_t a1, uint32_t a2, uint32_t a3,
    uint32_t b0, uint32_t b1)
{
    asm("mma.sync.aligned.m16n8k16.row.col.f32.bf16.bf16.f32 "
        "{%0,%1,%2,%3}, {%4,%5,%6,%7}, {%8,%9}, {%0,%1,%2,%3};"
        : "+f"(d[0]), "+f"(d[1]), "+f"(d[2]), "+f"(d[3])
        : "r"(a0), "r"(a1), "r"(a2), "r"(a3), "r"(b0), "r"(b1));
}
__device__ __forceinline__ void ldmx4(uint32_t* r, uint32_t addr){
    asm volatile("ldmatrix.sync.aligned.m8n8.x4.shared.b16 {%0,%1,%2,%3}, [%4];"
        : "=r"(r[0]), "=r"(r[1]), "=r"(r[2]), "=r"(r[3]) : "r"(addr));
}
__device__ __forceinline__ void ldmx2(uint32_t* r, uint32_t addr){
    asm volatile("ldmatrix.sync.aligned.m8n8.x2.shared.b16 {%0,%1}, [%2];"
        : "=r"(r[0]), "=r"(r[1]) : "r"(addr));
}
__device__ __forceinline__ uint32_t smem_u32(const void* p){
    uint32_t a;
    asm("{ .reg .u64 t; cvta.to.shared.u64 t, %1; cvt.u32.u64 %0, t; }" : "=r"(a) : "l"(p));
    return a;
}

// split fp32 -> (hi, lo) bf16 pair, packed as bf16x2 words
__device__ __forceinline__ void split2(float f0, float f1, uint32_t& hw, uint32_t& lw){
    __nv_bfloat16 h0 = __float2bfloat16_rn(f0);
    __nv_bfloat16 h1 = __float2bfloat16_rn(f1);
    __nv_bfloat16 l0 = __float2bfloat16_rn(f0 - __bfloat162float(h0));
    __nv_bfloat16 l1 = __float2bfloat16_rn(f1 - __bfloat162float(h1));
    hw = (uint32_t)*(uint16_t*)&h0 | ((uint32_t)*(uint16_t*)&h1 << 16);
    lw = (uint32_t)*(uint16_t*)&l0 | ((uint32_t)*(uint16_t*)&l1 << 16);
}

// ---------------------------------------------------------------------------
// Kernel 1: fused QKV projection on tensor cores (bf16 2-split, 3 passes).
// CTA 128(M) x 96(N); 512 threads, warps 4x4 -> warp tile 32x24.
// K slabs of 32; double-buffered smem + reg prefetch; ldmatrix frag loads.
// grid (6, 24) = 144 CTAs = 1 wave.
// Byte layout per buffer: AH@0 (128x80B) | AL@10240 | BH@20480 (96x80B) | BL@28160.
// ---------------------------------------------------------------------------
#define RSTR 40                    // bf16 row stride (80 bytes)
#define A_BYTES (128*80)           // 10240
#define B_BYTES (96*80)            // 7680
#define BUF_BYTES (2*A_BYTES + 2*B_BYTES)   // 35840
#define QKV_SMEM (2*BUF_BYTES)              // 71680

__global__ __launch_bounds__(512) void qkv_mma(
    const float* __restrict__ x,
    const float* __restrict__ Wq, const float* __restrict__ bq,
    const float* __restrict__ Wk, const float* __restrict__ bk,
    const float* __restrict__ Wv, const float* __restrict__ bv)
{
    extern __shared__ __nv_bfloat16 smb[];
    uint32_t* smw = (uint32_t*)smb;
    const uint32_t sb = smem_u32(smb);

    const int tid = threadIdx.x;
    const int wid = tid >> 5, lane = tid & 31;
    const int warp_m = wid >> 2, warp_n = wid & 3;

    const int m0 = blockIdx.x * 128;
    const int ntile = blockIdx.y;
    const int z = ntile >> 3;
    const int n0 = (ntile & 7) * 96;

    const float* W; const float* bias; float* out;
    if (z == 0)      { W = Wq; bias = bq; out = g_q; }
    else if (z == 1) { W = Wk; bias = bk; out = g_k; }
    else             { W = Wv; bias = bv; out = g_v; }

    float acc[2][3][4];
    #pragma unroll
    for (int mi = 0; mi < 2; mi++)
        #pragma unroll
        for (int j = 0; j < 3; j++)
            #pragma unroll
            for (int e = 0; e < 4; e++) acc[mi][j][e] = 0.f;

    // ---- ldmatrix per-lane base addresses (bytes) ----
    const int lrow = lane & 15;
    const int lkb  = (lane >> 4) * 16;                  // k-half byte offset
    const uint32_t aAddrH = sb + (uint32_t)((warp_m*32 + lrow) * 80 + lkb);
    const uint32_t aAddrL = aAddrH + A_BYTES;
    const int jrow  = warp_n*24 + ((lane >> 4) << 3) + (lane & 7);  // j-pair tiles
    const int jkb   = ((lane >> 3) & 1) * 16;
    const uint32_t b4AddrH = sb + 2*A_BYTES + (uint32_t)(jrow * 80 + jkb);
    const uint32_t b4AddrL = b4AddrH + B_BYTES;
    const int jrow2 = warp_n*24 + 16 + (lane & 7);                  // j2 tile
    const uint32_t b2AddrH = sb + 2*A_BYTES + (uint32_t)(jrow2 * 80 + jkb);
    const uint32_t b2AddrL = b2AddrH + B_BYTES;

    // ---- per-thread gmem load coords ----
    const int rA0 = tid >> 3,          qA0 = tid & 7;
    const int rA1 = (tid + 512) >> 3;
    const int rB0 = rA0;
    const int rB1 = rA1;
    const bool hasB1 = (tid < 256);

    float4 pa0, pa1, pb0, pb1;
    pa0 = *(const float4*)&x[(size_t)(m0 + rA0) * H + qA0 * 4];
    pa1 = *(const float4*)&x[(size_t)(m0 + rA1) * H + qA0 * 4];
    pb0 = *(const float4*)&W[(size_t)(n0 + rB0) * H + qA0 * 4];
    if (hasB1) pb1 = *(const float4*)&W[(size_t)(n0 + rB1) * H + qA0 * 4];

    for (int s = 0; s < 24; s++) {
        const uint32_t bufB = (s & 1) ? BUF_BYTES : 0;   // byte offset of buffer
        const uint32_t bofW = bufB >> 2;                  // word offset

        // ---- STS slab s ----
        {
            uint32_t h0,l0,h1,l1;
            split2(pa0.x, pa0.y, h0, l0); split2(pa0.z, pa0.w, h1, l1);
            int wo = rA0 * (RSTR/2) + qA0 * 2;
            *(uint2*)&smw[bofW + wo]              = make_uint2(h0, h1);
            *(uint2*)&smw[bofW + A_BYTES/4 + wo]  = make_uint2(l0, l1);
            split2(pa1.x, pa1.y, h0, l0); split2(pa1.z, pa1.w, h1, l1);
            wo = rA1 * (RSTR/2) + qA0 * 2;
            *(uint2*)&smw[bofW + wo]              = make_uint2(h0, h1);
            *(uint2*)&smw[bofW + A_BYTES/4 + wo]  = make_uint2(l0, l1);
            split2(pb0.x, pb0.y, h0, l0); split2(pb0.z, pb0.w, h1, l1);
            wo = rB0 * (RSTR/2) + qA0 * 2;
            *(uint2*)&smw[bofW + 2*(A_BYTES/4) + wo]              = make_uint2(h0, h1);
            *(uint2*)&smw[bofW + 2*(A_BYTES/4) + B_BYTES/4 + wo]  = make_uint2(l0, l1);
            if (hasB1) {
                split2(pb1.x, pb1.y, h0, l0); split2(pb1.z, pb1.w, h1, l1);
                wo = rB1 * (RSTR/2) + qA0 * 2;
                *(uint2*)&smw[bofW + 2*(A_BYTES/4) + wo]              = make_uint2(h0, h1);
                *(uint2*)&smw[bofW + 2*(A_BYTES/4) + B_BYTES/4 + wo]  = make_uint2(l0, l1);
            }
        }
        __syncthreads();

        // ---- prefetch slab s+1 (overlaps MMA) ----
        if (s < 23) {
            const int k0g = (s + 1) * 32;
            pa0 = *(const float4*)&x[(size_t)(m0 + rA0) * H + k0g + qA0 * 4];
            pa1 = *(const float4*)&x[(size_t)(m0 + rA1) * H + k0g + qA0 * 4];
            pb0 = *(const float4*)&W[(size_t)(n0 + rB0) * H + k0g + qA0 * 4];
            if (hasB1) pb1 = *(const float4*)&W[(size_t)(n0 + rB1) * H + k0g + qA0 * 4];
        }

        // ---- MMA slab s (ldmatrix fragment loads) ----
        #pragma unroll
        for (int ks = 0; ks < 2; ks++) {
            const uint32_t kb = bufB + ks * 32;
            uint32_t Ah[2][4], Al[2][4], B4h[4], B4l[4], B2h[2], B2l[2];
            ldmx4(Ah[0], aAddrH + kb);
            ldmx4(Ah[1], aAddrH + kb + 16*80);
            ldmx4(Al[0], aAddrL + kb);
            ldmx4(Al[1], aAddrL + kb + 16*80);
            ldmx4(B4h, b4AddrH + kb);
            ldmx4(B4l, b4AddrL + kb);
            ldmx2(B2h, b2AddrH + kb);
            ldmx2(B2l, b2AddrL + kb);
            #pragma unroll
            for (int mi = 0; mi < 2; mi++) {
                mma16816(acc[mi][0], Ah[mi][0],Ah[mi][1],Ah[mi][2],Ah[mi][3], B4h[0],B4h[1]);
                mma16816(acc[mi][0], Ah[mi][0],Ah[mi][1],Ah[mi][2],Ah[mi][3], B4l[0],B4l[1]);
                mma16816(acc[mi][0], Al[mi][0],Al[mi][1],Al[mi][2],Al[mi][3], B4h[0],B4h[1]);
                mma16816(acc[mi][1], Ah[mi][0],Ah[mi][1],Ah[mi][2],Ah[mi][3], B4h[2],B4h[3]);
                mma16816(acc[mi][1], Ah[mi][0],Ah[mi][1],Ah[mi][2],Ah[mi][3], B4l[2],B4l[3]);
                mma16816(acc[mi][1], Al[mi][0],Al[mi][1],Al[mi][2],Al[mi][3], B4h[2],B4h[3]);
                mma16816(acc[mi][2], Ah[mi][0],Ah[mi][1],Ah[mi][2],Ah[mi][3], B2h[0],B2h[1]);
                mma16816(acc[mi][2], Ah[mi][0],Ah[mi][1],Ah[mi][2],Ah[mi][3], B2l[0],B2l[1]);
                mma16816(acc[mi][2], Al[mi][0],Al[mi][1],Al[mi][2],Al[mi][3], B2h[0],B2h[1]);
            }
        }
    }

    // ---- epilogue ----
    const int gid = lane >> 2, tg = lane & 3;
    #pragma unroll
    for (int mi = 0; mi < 2; mi++) {
        int r0 = m0 + warp_m * 32 + mi * 16 + gid;
        #pragma unroll
        for (int j = 0; j < 3; j++) {
            int nc = n0 + warp_n * 24 + j * 8 + tg * 2;
            float b0 = bias[nc], b1 = bias[nc + 1];
            *(float2*)&out[(size_t)r0 * H + nc]       = make_float2(acc[mi][j][0] + b0, acc[mi][j][1] + b1);
            *(float2*)&out[(size_t)(r0 + 8) * H + nc] = make_float2(acc[mi][j][2] + b0, acc[mi][j][3] + b1);
        }
    }
}

// ---------------------------------------------------------------------------
// Kernel 2: attention with p=-2 distance scores.
// grid (6, 12, 2), block 512. Double-buffered K/V tiles (reg prefetch, one
// sync per tile). 4-way reciprocal pairing; Q,K scaled x4, compensated by
// score = -0.5 * acc^(-1/4).
// ---------------------------------------------------------------------------
#define QSTR 68
#define KSTR 68
#define SCW 385
#define ATTN_SMEM ((3*64*QSTR + 64*SCW + 64)*4)   // 151040 B

__global__ __launch_bounds__(512) void attn_kernel()
{
    extern __shared__ float sm[];
    float* qs  = sm;                       // [64][QSTR]
    float* kv0 = sm + 64*QSTR;             // tile buffer 0
    float* kv1 = kv0 + 64*QSTR;            // tile buffer 1
    float* sc  = kv1 + 64*QSTR;            // [64][SCW]
    float* rowsum = sc + 64*SCW;

    const int tid = threadIdx.x;
    const int b = blockIdx.z, h = blockIdx.y;
    const int i0 = blockIdx.x * 64;

    const float* Qb = g_q + (size_t)(b*SQ)*H + h*DHEAD;
    const float* Kb = g_k + (size_t)(b*SQ)*H + h*DHEAD;
    const float* Vb = g_v + (size_t)(b*SQ)*H + h*DHEAD;

    // Q tile [64][64], scaled by 4
    for (int idx = tid; idx < 64*16; idx += 512) {
        int i = idx >> 4, c4 = (idx & 15) << 2;
        float4 v = *(const float4*)&Qb[(size_t)(i0+i)*H + c4];
        v.x *= 4.f; v.y *= 4.f; v.z *= 4.f; v.w *= 4.f;
        *(float4*)&qs[i*QSTR + c4] = v;
    }

    const int tx = tid & 31;
    const int ty = tid >> 5;

    // per-thread tile-load coords (2 segs: tid, tid+512)
    const int kr0 = tid >> 4, kc0 = (tid & 15) << 2;
    const int kr1 = kr0 + 32;

    // ---- Phase 1: scores, double-buffered K tiles ----
    float4 pk0 = *(const float4*)&Kb[(size_t)(0 + kr0)*H + kc0];
    float4 pk1 = *(const float4*)&Kb[(size_t)(0 + kr1)*H + kc0];

    for (int jt = 0; jt < 6; jt++) {
        int j0 = jt * 64;
        float* kb = (jt & 1) ? kv1 : kv0;
        // STS transposed, negated, scaled
        kb[(kc0+0)*KSTR + kr0] = -4.f*pk0.x;
        kb[(kc0+1)*KSTR + kr0] = -4.f*pk0.y;
        kb[(kc0+2)*KSTR + kr0] = -4.f*pk0.z;
        kb[(kc0+3)*KSTR + kr0] = -4.f*pk0.w;
        kb[(kc0+0)*KSTR + kr1] = -4.f*pk1.x;
        kb[(kc0+1)*KSTR + kr1] = -4.f*pk1.y;
        kb[(kc0+2)*KSTR + kr1] = -4.f*pk1.z;
        kb[(kc0+3)*KSTR + kr1] = -4.f*pk1.w;
        __syncthreads();
        if (jt < 5) {
            pk0 = *(const float4*)&Kb[(size_t)(j0 + 64 + kr0)*H + kc0];
            pk1 = *(const float4*)&Kb[(size_t)(j0 + 64 + kr1)*H + kc0];
        }

        float2 acc[4];
        #pragma unroll
        for (int i = 0; i < 4; i++) acc[i] = make_float2(0.f, 0.f);

        #pragma unroll 4
        for (int d = 0; d < 64; d += 4) {
            float2 nk0 = *(const float2*)&kb[(d+0)*KSTR + tx*2];
            float2 nk1 = *(const float2*)&kb[(d+1)*KSTR + tx*2];
            float2 nk2 = *(const float2*)&kb[(d+2)*KSTR + tx*2];
            float2 nk3 = *(const float2*)&kb[(d+3)*KSTR + tx*2];
            #pragma unroll
            for (int i = 0; i < 4; i++) {
                float4 q = *(const float4*)&qs[(ty*4+i)*QSTR + d];
                float2 d0 = f2add(make_float2(q.x, q.x), nk0);
                float2 d1 = f2add(make_float2(q.y, q.y), nk1);
                float2 d2 = f2add(make_float2(q.z, q.z), nk2);
                float2 d3 = f2add(make_float2(q.w, q.w), nk3);
                float2 a  = f2mul(d0, d0);
                float2 bq2 = f2mul(d1, d1);
                float2 c  = f2mul(d2, d2);
                float2 e  = f2mul(d3, d3);
                float2 ab = f2mul(a, bq2);
                float2 ce = f2mul(c, e);
                float2 sab = f2add(a, bq2);
                float2 sce = f2add(c, e);
                float2 num = f2fma(sab, ce, f2mul(sce, ab));
                float2 den = f2mul(ab, ce);
                float2 r   = make_float2(frcp_approx(den.x), frcp_approx(den.y));
                acc[i] = f2fma(num, r, acc[i]);
            }
        }
        #pragma unroll
        for (int i = 0; i < 4; i++) {
            float* row = &sc[(ty*4+i)*SCW + j0 + tx*2];
            row[0] = -0.5f * frsqrt_approx(fsqrt_approx(acc[i].x));
            row[1] = -0.5f * frsqrt_approx(fsqrt_approx(acc[i].y));
        }
    }
    __syncthreads();

    // prefetch V tile 0 (hides LDG under softmax)
    float4 pv0 = *(const float4*)&Vb[(size_t)(0 + kr0)*H + kc0];
    float4 pv1 = *(const float4*)&Vb[(size_t)(0 + kr1)*H + kc0];

    // ---- Phase 2: softmax rows ----
    {
        const int wid = tid >> 5, lane = tid & 31;
        for (int i = wid; i < 64; i += 16) {
            float m = -3.402823466e38f;
            for (int j = lane; j < SQ; j += 32) m = fmaxf(m, sc[i*SCW + j]);
            #pragma unroll
            for (int o = 16; o; o >>= 1) m = fmaxf(m, __shfl_xor_sync(0xffffffffu, m, o));
            float s = 0.f;
            for (int j = lane; j < SQ; j += 32) {
                float p = __expf(sc[i*SCW + j] - m);
                sc[i*SCW + j] = p;
                s += p;
            }
            #pragma unroll
            for (int o = 16; o; o >>= 1) s += __shfl_xor_sync(0xffffffffu, s, o);
            if (lane == 0) rowsum[i] = s;
        }
    }
    __syncthreads();

    // ---- Phase 3: ctx = P @ V, double-buffered V tiles ----
    float2 acc2[4];
    #pragma unroll
    for (int i = 0; i < 4; i++) acc2[i] = make_float2(0.f, 0.f);

    for (int jt = 0; jt < 6; jt++) {
        int j0 = jt * 64;
        float* vb = (jt & 1) ? kv1 : kv0;
        *(float4*)&vb[kr0*QSTR + kc0] = pv0;
        *(float4*)&vb[kr1*QSTR + kc0] = pv1;
        __syncthreads();
        if (jt < 5) {
            pv0 = *(const float4*)&Vb[(size_t)(j0 + 64 + kr0)*H + kc0];
            pv1 = *(const float4*)&Vb[(size_t)(j0 + 64 + kr1)*H + kc0];
        }
        #pragma unroll 4
        for (int j = 0; j < 64; j++) {
            float2 vv = *(const float2*)&vb[j*QSTR + tx*2];
            #pragma unroll
            for (int i = 0; i < 4; i++) {
                float pvs = sc[(ty*4+i)*SCW + j0 + j];
                acc2[i] = f2fma(make_float2(pvs, pvs), vv, acc2[i]);
            }
        }
    }

    #pragma unroll
    for (int i = 0; i < 4; i++) {
        float rs = frcp_approx(rowsum[ty*4 + i]);
        int row = i0 + ty*4 + i;
        float* op = &g_ctx[(size_t)(b*SQ + row)*H + h*DHEAD + tx*2];
        op[0] = acc2[i].x * rs;
        op[1] = acc2[i].y * rs;
    }
}

// ---------------------------------------------------------------------------
// Kernel 3: residual + LayerNorm.
// ---------------------------------------------------------------------------
__global__ __launch_bounds__(256) void ln_kernel(
    const float* __restrict__ x, const float* __restrict__ gam,
    const float* __restrict__ bet, float* __restrict__ out)
{
    const int r = blockIdx.x;
    const float* xr = x + (size_t)r * H;
    const float* cr = g_ctx + (size_t)r * H;
    const int tid = threadIdx.x;

    __shared__ float redS[8], redQ[8];

    float y[3];
    float s = 0.f, ss = 0.f;
    #pragma unroll
    for (int k = 0; k < 3; k++) {
        int j = tid + k * 256;
        y[k] = xr[j] + cr[j];
        s += y[k];
        ss += y[k] * y[k];
    }
    #pragma unroll
    for (int o = 16; o; o >>= 1) {
        s  += __shfl_xor_sync(0xffffffffu, s, o);
        ss += __shfl_xor_sync(0xffffffffu, ss, o);
    }
    const int wid = tid >> 5, lane = tid & 31;
    if (lane == 0) { redS[wid] = s; redQ[wid] = ss; }
    __syncthreads();
    if (tid == 0) {
        float a = 0.f, b2 = 0.f;
        #pragma unroll
        for (int w = 0; w < 8; w++) { a += redS[w]; b2 += redQ[w]; }
        redS[0] = a; redQ[0] = b2;
    }
    __syncthreads();
    const float mu  = redS[0] * (1.f / (float)H);
    const float var = redQ[0] * (1.f / (float)H) - mu * mu;
    const float inv = rsqrtf(var + 1e-12f);

    #pragma unroll
    for (int k = 0; k < 3; k++) {
        int j = tid + k * 256;
        out[(size_t)r * H + j] = (y[k] - mu) * inv * gam[j] + bet[j];
    }
}

// ---------------------------------------------------------------------------
extern "C" void kernel_launch(void* const* d_in, const int* in_sizes, int n_in,
                              void* d_out, int out_size)
{
    const float* x   = (const float*)d_in[0];
    const float* Wq  = (const float*)d_in[1];
    const float* bq  = (const float*)d_in[2];
    const float* Wk  = (const float*)d_in[3];
    const float* bk  = (const float*)d_in[4];
    const float* Wv  = (const float*)d_in[5];
    const float* bv  = (const float*)d_in[6];
    const float* lng = (const float*)d_in[7];
    const float* lnb = (const float*)d_in[8];
    float* out = (float*)d_out;

    // 1) fused QKV projection on tensor cores: grid (6, 24) = 144 CTAs
    cudaFuncSetAttribute(qkv_mma, cudaFuncAttributeMaxDynamicSharedMemorySize, QKV_SMEM);
    qkv_mma<<<dim3(6, 24), 512, QKV_SMEM>>>(x, Wq, bq, Wk, bk, Wv, bv);

    // 2) attention
    cudaFuncSetAttribute(attn_kernel, cudaFuncAttributeMaxDynamicSharedMemorySize, ATTN_SMEM);
    attn_kernel<<<dim3(6, NHEADS, BB), 512, ATTN_SMEM>>>();

    // 3) residual + LayerNorm
    ln_kernel<<<BS, 256>>>(x, lng, lnb, out);
}

// round 12
// speedup vs baseline: 2.0515x; 1.0007x over previous
#include <cuda_runtime.h>
#include <cuda_bf16.h>
#include <cstdint>

#define H 768
#define SQ 384
#define BB 2
#define NHEADS 12
#define DHEAD 64
#define BS (BB*SQ)   // 768 rows total

// Scratch (allocation-free rule: __device__ globals)
__device__ float g_q[BS*H];
__device__ float g_k[BS*H];
__device__ float g_v[BS*H];
__device__ float g_ctx[BS*H];

__device__ __forceinline__ float frcp_approx(float x){ float r; asm("rcp.approx.ftz.f32 %0, %1;" : "=f"(r) : "f"(x)); return r; }
__device__ __forceinline__ float fsqrt_approx(float x){ float r; asm("sqrt.approx.f32 %0, %1;" : "=f"(r) : "f"(x)); return r; }
__device__ __forceinline__ float frsqrt_approx(float x){ float r; asm("rsqrt.approx.f32 %0, %1;" : "=f"(r) : "f"(x)); return r; }

// ---- packed fp32x2 ops ----
union F2U { float2 f; unsigned long long u; };
__device__ __forceinline__ float2 f2fma(float2 a, float2 b, float2 c){
    F2U A, Bv, C, R; A.f = a; Bv.f = b; C.f = c;
    asm("fma.rn.f32x2 %0, %1, %2, %3;" : "=l"(R.u) : "l"(A.u), "l"(Bv.u), "l"(C.u));
    return R.f;
}
__device__ __forceinline__ float2 f2add(float2 a, float2 b){
    F2U A, Bv, R; A.f = a; Bv.f = b;
    asm("add.rn.f32x2 %0, %1, %2;" : "=l"(R.u) : "l"(A.u), "l"(Bv.u));
    return R.f;
}
__device__ __forceinline__ float2 f2mul(float2 a, float2 b){
    F2U A, Bv, R; A.f = a; Bv.f = b;
    asm("mul.rn.f32x2 %0, %1, %2;" : "=l"(R.u) : "l"(A.u), "l"(Bv.u));
    return R.f;
}

// ---- warp-level bf16 MMA + ldmatrix (HMMA/LDSM path, base sm_100 OK) ----
__device__ __forceinline__ void mma16816(float* d,
    uint32_t a0, uint32_t a1, uint32_t a2, uint32_t a3,
    uint32_t b0, uint32_t b1)
{
    asm("mma.sync.aligned.m16n8k16.row.col.f32.bf16.bf16.f32 "
        "{%0,%1,%2,%3}, {%4,%5,%6,%7}, {%8,%9}, {%0,%1,%2,%3};"
        : "+f"(d[0]), "+f"(d[1]), "+f"(d[2]), "+f"(d[3])
        : "r"(a0), "r"(a1), "r"(a2), "r"(a3), "r"(b0), "r"(b1));
}
__device__ __forceinline__ void ldmx4(uint32_t* r, uint32_t addr){
    asm volatile("ldmatrix.sync.aligned.m8n8.x4.shared.b16 {%0,%1,%2,%3}, [%4];"
        : "=r"(r[0]), "=r"(r[1]), "=r"(r[2]), "=r"(r[3]) : "r"(addr));
}
__device__ __forceinline__ void ldmx2(uint32_t* r, uint32_t addr){
    asm volatile("ldmatrix.sync.aligned.m8n8.x2.shared.b16 {%0,%1}, [%2];"
        : "=r"(r[0]), "=r"(r[1]) : "r"(addr));
}
__device__ __forceinline__ uint32_t smem_u32(const void* p){
    uint32_t a;
    asm("{ .reg .u64 t; cvta.to.shared.u64 t, %1; cvt.u32.u64 %0, t; }" : "=r"(a) : "l"(p));
    return a;
}

// split fp32 -> (hi, lo) bf16 pair, packed as bf16x2 words
__device__ __forceinline__ void split2(float f0, float f1, uint32_t& hw, uint32_t& lw){
    __nv_bfloat16 h0 = __float2bfloat16_rn(f0);
    __nv_bfloat16 h1 = __float2bfloat16_rn(f1);
    __nv_bfloat16 l0 = __float2bfloat16_rn(f0 - __bfloat162float(h0));
    __nv_bfloat16 l1 = __float2bfloat16_rn(f1 - __bfloat162float(h1));
    hw = (uint32_t)*(uint16_t*)&h0 | ((uint32_t)*(uint16_t*)&h1 << 16);
    lw = (uint32_t)*(uint16_t*)&l0 | ((uint32_t)*(uint16_t*)&l1 << 16);
}

// ---------------------------------------------------------------------------
// Kernel 1: fused QKV projection on tensor cores (bf16 2-split, 3 passes).
// CTA 64(M) x 96(N); 256 threads, 8 warps as 2(M) x 4(N) -> warp tile 32x24.
// grid (12, 24) = 288 CTAs -> TWO independent CTAs per SM: while one CTA
// sits in its per-slab barrier / LDSM latency, the other feeds the tensor
// pipe. K slabs of 32; double-buffered smem + reg prefetch; ldmatrix.
// Byte layout per buffer: AH@0 (64x80B) | AL@5120 | BH@10240 (96x80B) | BL@17920.
// ---------------------------------------------------------------------------
#define RSTR 40                    // bf16 row stride (80 bytes)
#define A_BYTES (64*80)            // 5120
#define B_BYTES (96*80)            // 7680
#define BUF_BYTES (2*A_BYTES + 2*B_BYTES)   // 25600
#define QKV_SMEM (2*BUF_BYTES)              // 51200 -> 2 CTAs/SM

__global__ __launch_bounds__(256) void qkv_mma(
    const float* __restrict__ x,
    const float* __restrict__ Wq, const float* __restrict__ bq,
    const float* __restrict__ Wk, const float* __restrict__ bk,
    const float* __restrict__ Wv, const float* __restrict__ bv)
{
    extern __shared__ __nv_bfloat16 smb[];
    uint32_t* smw = (uint32_t*)smb;
    const uint32_t sb = smem_u32(smb);

    const int tid = threadIdx.x;
    const int wid = tid >> 5, lane = tid & 31;
    const int warp_m = wid >> 2, warp_n = wid & 3;

    const int m0 = blockIdx.x * 64;
    const int ntile = blockIdx.y;
    const int z = ntile >> 3;
    const int n0 = (ntile & 7) * 96;

    const float* W; const float* bias; float* out;
    if (z == 0)      { W = Wq; bias = bq; out = g_q; }
    else if (z == 1) { W = Wk; bias = bk; out = g_k; }
    else             { W = Wv; bias = bv; out = g_v; }

    float acc[2][3][4];
    #pragma unroll
    for (int mi = 0; mi < 2; mi++)
        #pragma unroll
        for (int j = 0; j < 3; j++)
            #pragma unroll
            for (int e = 0; e < 4; e++) acc[mi][j][e] = 0.f;

    // ---- ldmatrix per-lane base addresses (bytes) ----
    const int lrow = lane & 15;
    const int lkb  = (lane >> 4) * 16;                  // k-half byte offset
    const uint32_t aAddrH = sb + (uint32_t)((warp_m*32 + lrow) * 80 + lkb);
    const uint32_t aAddrL = aAddrH + A_BYTES;
    const int jrow  = warp_n*24 + ((lane >> 4) << 3) + (lane & 7);  // j-pair tiles
    const int jkb   = ((lane >> 3) & 1) * 16;
    const uint32_t b4AddrH = sb + 2*A_BYTES + (uint32_t)(jrow * 80 + jkb);
    const uint32_t b4AddrL = b4AddrH + B_BYTES;
    const int jrow2 = warp_n*24 + 16 + (lane & 7);                  // j2 tile
    const uint32_t b2AddrH = sb + 2*A_BYTES + (uint32_t)(jrow2 * 80 + jkb);
    const uint32_t b2AddrL = b2AddrH + B_BYTES;

    // ---- per-thread gmem load coords (256 threads) ----
    // A: 64x32 = 512 16B-segs -> 2/thread. B: 96x32 = 768 segs -> 3/thread.
    const int qseg = tid & 7;                 // 16B column within slab
    const int rA0 = tid >> 3;                 // 0..31
    const int rA1 = rA0 + 32;                 // 32..63
    const int rB0 = rA0;                      // 0..31
    const int rB1 = rA0 + 32;                 // 32..63
    const int rB2 = rA0 + 64;                 // 64..95

    float4 pa0, pa1, pb0, pb1, pb2;
    pa0 = *(const float4*)&x[(size_t)(m0 + rA0) * H + qseg * 4];
    pa1 = *(const float4*)&x[(size_t)(m0 + rA1) * H + qseg * 4];
    pb0 = *(const float4*)&W[(size_t)(n0 + rB0) * H + qseg * 4];
    pb1 = *(const float4*)&W[(size_t)(n0 + rB1) * H + qseg * 4];
    pb2 = *(const float4*)&W[(size_t)(n0 + rB2) * H + qseg * 4];

    for (int s = 0; s < 24; s++) {
        const uint32_t bufB = (s & 1) ? BUF_BYTES : 0;   // byte offset of buffer
        const uint32_t bofW = bufB >> 2;                  // word offset

        // ---- STS slab s ----
        {
            uint32_t h0,l0,h1,l1;
            split2(pa0.x, pa0.y, h0, l0); split2(pa0.z, pa0.w, h1, l1);
            int wo = rA0 * (RSTR/2) + qseg * 2;
            *(uint2*)&smw[bofW + wo]              = make_uint2(h0, h1);
            *(uint2*)&smw[bofW + A_BYTES/4 + wo]  = make_uint2(l0, l1);
            split2(pa1.x, pa1.y, h0, l0); split2(pa1.z, pa1.w, h1, l1);
            wo = rA1 * (RSTR/2) + qseg * 2;
            *(uint2*)&smw[bofW + wo]              = make_uint2(h0, h1);
            *(uint2*)&smw[bofW + A_BYTES/4 + wo]  = make_uint2(l0, l1);
            split2(pb0.x, pb0.y, h0, l0); split2(pb0.z, pb0.w, h1, l1);
            wo = rB0 * (RSTR/2) + qseg * 2;
            *(uint2*)&smw[bofW + 2*(A_BYTES/4) + wo]              = make_uint2(h0, h1);
            *(uint2*)&smw[bofW + 2*(A_BYTES/4) + B_BYTES/4 + wo]  = make_uint2(l0, l1);
            split2(pb1.x, pb1.y, h0, l0); split2(pb1.z, pb1.w, h1, l1);
            wo = rB1 * (RSTR/2) + qseg * 2;
            *(uint2*)&smw[bofW + 2*(A_BYTES/4) + wo]              = make_uint2(h0, h1);
            *(uint2*)&smw[bofW + 2*(A_BYTES/4) + B_BYTES/4 + wo]  = make_uint2(l0, l1);
            split2(pb2.x, pb2.y, h0, l0); split2(pb2.z, pb2.w, h1, l1);
            wo = rB2 * (RSTR/2) + qseg * 2;
            *(uint2*)&smw[bofW + 2*(A_BYTES/4) + wo]              = make_uint2(h0, h1);
            *(uint2*)&smw[bofW + 2*(A_BYTES/4) + B_BYTES/4 + wo]  = make_uint2(l0, l1);
        }
        __syncthreads();

        // ---- prefetch slab s+1 (overlaps MMA) ----
        if (s < 23) {
            const int k0g = (s + 1) * 32;
            pa0 = *(const float4*)&x[(size_t)(m0 + rA0) * H + k0g + qseg * 4];
            pa1 = *(const float4*)&x[(size_t)(m0 + rA1) * H + k0g + qseg * 4];
            pb0 = *(const float4*)&W[(size_t)(n0 + rB0) * H + k0g + qseg * 4];
            pb1 = *(const float4*)&W[(size_t)(n0 + rB1) * H + k0g + qseg * 4];
            pb2 = *(const float4*)&W[(size_t)(n0 + rB2) * H + k0g + qseg * 4];
        }

        // ---- MMA slab s (ldmatrix fragment loads) ----
        #pragma unroll
        for (int ks = 0; ks < 2; ks++) {
            const uint32_t kb = bufB + ks * 32;
            uint32_t Ah[2][4], Al[2][4], B4h[4], B4l[4], B2h[2], B2l[2];
            ldmx4(Ah[0], aAddrH + kb);
            ldmx4(Ah[1], aAddrH + kb + 16*80);
            ldmx4(Al[0], aAddrL + kb);
            ldmx4(Al[1], aAddrL + kb + 16*80);
            ldmx4(B4h, b4AddrH + kb);
            ldmx4(B4l, b4AddrL + kb);
            ldmx2(B2h, b2AddrH + kb);
            ldmx2(B2l, b2AddrL + kb);
            #pragma unroll
            for (int mi = 0; mi < 2; mi++) {
                mma16816(acc[mi][0], Ah[mi][0],Ah[mi][1],Ah[mi][2],Ah[mi][3], B4h[0],B4h[1]);
                mma16816(acc[mi][0], Ah[mi][0],Ah[mi][1],Ah[mi][2],Ah[mi][3], B4l[0],B4l[1]);
                mma16816(acc[mi][0], Al[mi][0],Al[mi][1],Al[mi][2],Al[mi][3], B4h[0],B4h[1]);
                mma16816(acc[mi][1], Ah[mi][0],Ah[mi][1],Ah[mi][2],Ah[mi][3], B4h[2],B4h[3]);
                mma16816(acc[mi][1], Ah[mi][0],Ah[mi][1],Ah[mi][2],Ah[mi][3], B4l[2],B4l[3]);
                mma16816(acc[mi][1], Al[mi][0],Al[mi][1],Al[mi][2],Al[mi][3], B4h[2],B4h[3]);
                mma16816(acc[mi][2], Ah[mi][0],Ah[mi][1],Ah[mi][2],Ah[mi][3], B2h[0],B2h[1]);
                mma16816(acc[mi][2], Ah[mi][0],Ah[mi][1],Ah[mi][2],Ah[mi][3], B2l[0],B2l[1]);
                mma16816(acc[mi][2], Al[mi][0],Al[mi][1],Al[mi][2],Al[mi][3], B2h[0],B2h[1]);
            }
        }
    }

    // ---- epilogue ----
    const int gid = lane >> 2, tg = lane & 3;
    #pragma unroll
    for (int mi = 0; mi < 2; mi++) {
        int r0 = m0 + warp_m * 32 + mi * 16 + gid;
        #pragma unroll
        for (int j = 0; j < 3; j++) {
            int nc = n0 + warp_n * 24 + j * 8 + tg * 2;
            float b0 = bias[nc], b1 = bias[nc + 1];
            *(float2*)&out[(size_t)r0 * H + nc]       = make_float2(acc[mi][j][0] + b0, acc[mi][j][1] + b1);
            *(float2*)&out[(size_t)(r0 + 8) * H + nc] = make_float2(acc[mi][j][2] + b0, acc[mi][j][3] + b1);
        }
    }
}

// ---------------------------------------------------------------------------
// Kernel 2: attention with p=-2 distance scores (unchanged from round 11).
// ---------------------------------------------------------------------------
#define QSTR 68
#define KSTR 68
#define SCW 385
#define ATTN_SMEM ((3*64*QSTR + 64*SCW + 64)*4)   // 151040 B

__global__ __launch_bounds__(512) void attn_kernel()
{
    extern __shared__ float sm[];
    float* qs  = sm;                       // [64][QSTR]
    float* kv0 = sm + 64*QSTR;             // tile buffer 0
    float* kv1 = kv0 + 64*QSTR;            // tile buffer 1
    float* sc  = kv1 + 64*QSTR;            // [64][SCW]
    float* rowsum = sc + 64*SCW;

    const int tid = threadIdx.x;
    const int b = blockIdx.z, h = blockIdx.y;
    const int i0 = blockIdx.x * 64;

    const float* Qb = g_q + (size_t)(b*SQ)*H + h*DHEAD;
    const float* Kb = g_k + (size_t)(b*SQ)*H + h*DHEAD;
    const float* Vb = g_v + (size_t)(b*SQ)*H + h*DHEAD;

    // Q tile [64][64], scaled by 4
    for (int idx = tid; idx < 64*16; idx += 512) {
        int i = idx >> 4, c4 = (idx & 15) << 2;
        float4 v = *(const float4*)&Qb[(size_t)(i0+i)*H + c4];
        v.x *= 4.f; v.y *= 4.f; v.z *= 4.f; v.w *= 4.f;
        *(float4*)&qs[i*QSTR + c4] = v;
    }

    const int tx = tid & 31;
    const int ty = tid >> 5;

    // per-thread tile-load coords (2 segs: tid, tid+512)
    const int kr0 = tid >> 4, kc0 = (tid & 15) << 2;
    const int kr1 = kr0 + 32;

    // ---- Phase 1: scores, double-buffered K tiles ----
    float4 pk0 = *(const float4*)&Kb[(size_t)(0 + kr0)*H + kc0];
    float4 pk1 = *(const float4*)&Kb[(size_t)(0 + kr1)*H + kc0];

    for (int jt = 0; jt < 6; jt++) {
        int j0 = jt * 64;
        float* kb = (jt & 1) ? kv1 : kv0;
        // STS transposed, negated, scaled
        kb[(kc0+0)*KSTR + kr0] = -4.f*pk0.x;
        kb[(kc0+1)*KSTR + kr0] = -4.f*pk0.y;
        kb[(kc0+2)*KSTR + kr0] = -4.f*pk0.z;
        kb[(kc0+3)*KSTR + kr0] = -4.f*pk0.w;
        kb[(kc0+0)*KSTR + kr1] = -4.f*pk1.x;
        kb[(kc0+1)*KSTR + kr1] = -4.f*pk1.y;
        kb[(kc0+2)*KSTR + kr1] = -4.f*pk1.z;
        kb[(kc0+3)*KSTR + kr1] = -4.f*pk1.w;
        __syncthreads();
        if (jt < 5) {
            pk0 = *(const float4*)&Kb[(size_t)(j0 + 64 + kr0)*H + kc0];
            pk1 = *(const float4*)&Kb[(size_t)(j0 + 64 + kr1)*H + kc0];
        }

        float2 acc[4];
        #pragma unroll
        for (int i = 0; i < 4; i++) acc[i] = make_float2(0.f, 0.f);

        #pragma unroll 4
        for (int d = 0; d < 64; d += 4) {
            float2 nk0 = *(const float2*)&kb[(d+0)*KSTR + tx*2];
            float2 nk1 = *(const float2*)&kb[(d+1)*KSTR + tx*2];
            float2 nk2 = *(const float2*)&kb[(d+2)*KSTR + tx*2];
            float2 nk3 = *(const float2*)&kb[(d+3)*KSTR + tx*2];
            #pragma unroll
            for (int i = 0; i < 4; i++) {
                float4 q = *(const float4*)&qs[(ty*4+i)*QSTR + d];
                float2 d0 = f2add(make_float2(q.x, q.x), nk0);
                float2 d1 = f2add(make_float2(q.y, q.y), nk1);
                float2 d2 = f2add(make_float2(q.z, q.z), nk2);
                float2 d3 = f2add(make_float2(q.w, q.w), nk3);
                float2 a  = f2mul(d0, d0);
                float2 bq2 = f2mul(d1, d1);
                float2 c  = f2mul(d2, d2);
                float2 e  = f2mul(d3, d3);
                float2 ab = f2mul(a, bq2);
                float2 ce = f2mul(c, e);
                float2 sab = f2add(a, bq2);
                float2 sce = f2add(c, e);
                float2 num = f2fma(sab, ce, f2mul(sce, ab));
                float2 den = f2mul(ab, ce);
                float2 r   = make_float2(frcp_approx(den.x), frcp_approx(den.y));
                acc[i] = f2fma(num, r, acc[i]);
            }
        }
        #pragma unroll
        for (int i = 0; i < 4; i++) {
            float* row = &sc[(ty*4+i)*SCW + j0 + tx*2];
            row[0] = -0.5f * frsqrt_approx(fsqrt_approx(acc[i].x));
            row[1] = -0.5f * frsqrt_approx(fsqrt_approx(acc[i].y));
        }
    }
    __syncthreads();

    // prefetch V tile 0 (hides LDG under softmax)
    float4 pv0 = *(const float4*)&Vb[(size_t)(0 + kr0)*H + kc0];
    float4 pv1 = *(const float4*)&Vb[(size_t)(0 + kr1)*H + kc0];

    // ---- Phase 2: softmax rows ----
    {
        const int wid = tid >> 5, lane = tid & 31;
        for (int i = wid; i < 64; i += 16) {
            float m = -3.402823466e38f;
            for (int j = lane; j < SQ; j += 32) m = fmaxf(m, sc[i*SCW + j]);
            #pragma unroll
            for (int o = 16; o; o >>= 1) m = fmaxf(m, __shfl_xor_sync(0xffffffffu, m, o));
            float s = 0.f;
            for (int j = lane; j < SQ; j += 32) {
                float p = __expf(sc[i*SCW + j] - m);
                sc[i*SCW + j] = p;
                s += p;
            }
            #pragma unroll
            for (int o = 16; o; o >>= 1) s += __shfl_xor_sync(0xffffffffu, s, o);
            if (lane == 0) rowsum[i] = s;
        }
    }
    __syncthreads();

    // ---- Phase 3: ctx = P @ V, double-buffered V tiles ----
    float2 acc2[4];
    #pragma unroll
    for (int i = 0; i < 4; i++) acc2[i] = make_float2(0.f, 0.f);

    for (int jt = 0; jt < 6; jt++) {
        int j0 = jt * 64;
        float* vb = (jt & 1) ? kv1 : kv0;
        *(float4*)&vb[kr0*QSTR + kc0] = pv0;
        *(float4*)&vb[kr1*QSTR + kc0] = pv1;
        __syncthreads();
        if (jt < 5) {
            pv0 = *(const float4*)&Vb[(size_t)(j0 + 64 + kr0)*H + kc0];
            pv1 = *(const float4*)&Vb[(size_t)(j0 + 64 + kr1)*H + kc0];
        }
        #pragma unroll 4
        for (int j = 0; j < 64; j++) {
            float2 vv = *(const float2*)&vb[j*QSTR + tx*2];
            #pragma unroll
            for (int i = 0; i < 4; i++) {
                float pvs = sc[(ty*4+i)*SCW + j0 + j];
                acc2[i] = f2fma(make_float2(pvs, pvs), vv, acc2[i]);
            }
        }
    }

    #pragma unroll
    for (int i = 0; i < 4; i++) {
        float rs = frcp_approx(rowsum[ty*4 + i]);
        int row = i0 + ty*4 + i;
        float* op = &g_ctx[(size_t)(b*SQ + row)*H + h*DHEAD + tx*2];
        op[0] = acc2[i].x * rs;
        op[1] = acc2[i].y * rs;
    }
}

// ---------------------------------------------------------------------------
// Kernel 3: residual + LayerNorm.
// ---------------------------------------------------------------------------
__global__ __launch_bounds__(256) void ln_kernel(
    const float* __restrict__ x, const float* __restrict__ gam,
    const float* __restrict__ bet, float* __restrict__ out)
{
    const int r = blockIdx.x;
    const float* xr = x + (size_t)r * H;
    const float* cr = g_ctx + (size_t)r * H;
    const int tid = threadIdx.x;

    __shared__ float redS[8], redQ[8];

    float y[3];
    float s = 0.f, ss = 0.f;
    #pragma unroll
    for (int k = 0; k < 3; k++) {
        int j = tid + k * 256;
        y[k] = xr[j] + cr[j];
        s += y[k];
        ss += y[k] * y[k];
    }
    #pragma unroll
    for (int o = 16; o; o >>= 1) {
        s  += __shfl_xor_sync(0xffffffffu, s, o);
        ss += __shfl_xor_sync(0xffffffffu, ss, o);
    }
    const int wid = tid >> 5, lane = tid & 31;
    if (lane == 0) { redS[wid] = s; redQ[wid] = ss; }
    __syncthreads();
    if (tid == 0) {
        float a = 0.f, b2 = 0.f;
        #pragma unroll
        for (int w = 0; w < 8; w++) { a += redS[w]; b2 += redQ[w]; }
        redS[0] = a; redQ[0] = b2;
    }
    __syncthreads();
    const float mu  = redS[0] * (1.f / (float)H);
    const float var = redQ[0] * (1.f / (float)H) - mu * mu;
    const float inv = rsqrtf(var + 1e-12f);

    #pragma unroll
    for (int k = 0; k < 3; k++) {
        int j = tid + k * 256;
        out[(size_t)r * H + j] = (y[k] - mu) * inv * gam[j] + bet[j];
    }
}

// ---------------------------------------------------------------------------
extern "C" void kernel_launch(void* const* d_in, const int* in_sizes, int n_in,
                              void* d_out, int out_size)
{
    const float* x   = (const float*)d_in[0];
    const float* Wq  = (const float*)d_in[1];
    const float* bq  = (const float*)d_in[2];
    const float* Wk  = (const float*)d_in[3];
    const float* bk  = (const float*)d_in[4];
    const float* Wv  = (const float*)d_in[5];
    const float* bv  = (const float*)d_in[6];
    const float* lng = (const float*)d_in[7];
    const float* lnb = (const float*)d_in[8];
    float* out = (float*)d_out;

    // 1) fused QKV projection on tensor cores: grid (12, 24) = 288 CTAs, 2/SM
    cudaFuncSetAttribute(qkv_mma, cudaFuncAttributeMaxDynamicSharedMemorySize, QKV_SMEM);
    qkv_mma<<<dim3(12, 24), 256, QKV_SMEM>>>(x, Wq, bq, Wk, bk, Wv, bv);

    // 2) attention
    cudaFuncSetAttribute(attn_kernel, cudaFuncAttributeMaxDynamicSharedMemorySize, ATTN_SMEM);
    attn_kernel<<<dim3(6, NHEADS, BB), 512, ATTN_SMEM>>>();

    // 3) residual + LayerNorm
    ln_kernel<<<BS, 256>>>(x, lng, lnb, out);
}